// round 14
// baseline (speedup 1.0000x reference)
#include <cuda_runtime.h>
#include <cuda_bf16.h>
#include <cstdint>
#include <cstddef>

// Problem constants
#define BB 16
#define NN_ 512
#define DD 256
#define HH 8
#define DHH 32
#define EE 16384
#define BN (BB * NN_)          // 8192

// Output layout (flattened tuple, in reference return order)
#define O_AIMG 0
#define O_ATXT 2097152
#define O_XMOD 4194304
#define O_IW   6291456
#define O_TW   10485760
#define O_IC   14680064
#define O_TC   14688256

// -------------------- static scratch (no allocations allowed) --------------------
__device__ float g_qkv0[BN * 768];
__device__ float g_qkv1[BN * 768];
__device__ float g_attn0[BN * DD];   // fa writes tf32-rounded
__device__ float g_attn1[BN * DD];
__device__ float g_G1i[BN * DD];
__device__ float g_G2i[BN * DD];
__device__ float g_G1t[BN * DD];
__device__ float g_G2t[BN * DD];
__device__ float g_H0[BN * DD];
__device__ float g_H1[BN * DD];
// tf32-pre-rounded copies of GEMM inputs
__device__ float g_imgR[BN * DD];
__device__ float g_txtR[BN * DD];
__device__ float g_w1R[512 * 256];
__device__ float g_inwR[768 * 256];
__device__ float g_outwR[256 * 256];
__device__ float g_cw1R[256 * 256];
__device__ float g_aimgR[BN * DD];
__device__ float g_atxtR[BN * DD];
// sparse-mask support (edges bucketed by exact src; tile prefixes at s=64k)
__device__ float g_eval[2 * BB * EE];
__device__ int   g_eoff[513];
__device__ int   g_elist[EE];

__device__ __forceinline__ uint32_t f32_to_tf32(float x) {
    uint32_t r;
    asm("cvt.rna.tf32.f32 %0, %1;" : "=r"(r) : "f"(x));
    return r;
}
__device__ __forceinline__ float round_tf32(float x) {
    return __uint_as_float(f32_to_tf32(x));
}

__device__ __forceinline__ void mma_tf32(float* d, const uint32_t* a, const uint32_t* b) {
    asm volatile(
        "mma.sync.aligned.m16n8k8.row.col.f32.tf32.tf32.f32 "
        "{%0,%1,%2,%3}, {%4,%5,%6,%7}, {%8,%9}, {%0,%1,%2,%3};"
        : "+f"(d[0]), "+f"(d[1]), "+f"(d[2]), "+f"(d[3])
        : "r"(a[0]), "r"(a[1]), "r"(a[2]), "r"(a[3]), "r"(b[0]), "r"(b[1]));
}

__device__ __forceinline__ void ldsm_x4(uint32_t& r0, uint32_t& r1, uint32_t& r2,
                                        uint32_t& r3, uint32_t saddr) {
    asm volatile("ldmatrix.sync.aligned.m8n8.x4.shared.b16 {%0,%1,%2,%3}, [%4];"
                 : "=r"(r0), "=r"(r1), "=r"(r2), "=r"(r3) : "r"(saddr));
}

__device__ __forceinline__ void cp_async16(void* smem, const void* gmem) {
    uint32_t s = (uint32_t)__cvta_generic_to_shared(smem);
    asm volatile("cp.async.ca.shared.global [%0], [%1], 16;" :: "r"(s), "l"(gmem));
}
__device__ __forceinline__ void cp_commit() {
    asm volatile("cp.async.commit_group;");
}
template <int N>
__device__ __forceinline__ void cp_wait() {
    asm volatile("cp.async.wait_group %0;" :: "n"(N));
}

// ---------------- pre-round kernel: d[i] = tf32(s[i]) -----------------------------
struct RoundBatch { const float* s[6]; float* d[6]; int n[6]; };
__global__ __launch_bounds__(256)
void round_kernel(RoundBatch rb)
{
    const int z = blockIdx.y;
    const float* s = rb.s[z];
    float* d = rb.d[z];
    const int n4 = rb.n[z] >> 2;
    const int stride = gridDim.x * 256;
    for (int i = blockIdx.x * 256 + threadIdx.x; i < n4; i += stride) {
        float4 v = *(const float4*)(s + i * 4);
        v.x = round_tf32(v.x); v.y = round_tf32(v.y);
        v.z = round_tf32(v.z); v.w = round_tf32(v.w);
        *(float4*)(d + i * 4) = v;
    }
}

// ---------------- bucket kernel: sort edge ids by exact src -----------------------
__global__ __launch_bounds__(512)
void bucket_kernel(const int* __restrict__ src)
{
    __shared__ int cnt[512];
    __shared__ int base[512];
    const int tid = threadIdx.x;
    cnt[tid] = 0;
    __syncthreads();
    for (int e = tid; e < EE; e += 512) atomicAdd(&cnt[src[e]], 1);
    __syncthreads();
    if (tid == 0) {
        int s = 0;
        for (int t = 0; t < 512; t++) { base[t] = s; g_eoff[t] = s; s += cnt[t]; }
        g_eoff[512] = s;
    }
    __syncthreads();
    for (int e = tid; e < EE; e += 512) {
        const int pos = atomicAdd(&base[src[e]], 1);
        g_elist[pos] = e;
    }
}

// ===================== batched, pipelined TF32 tensor-core GEMM ====================
// CTA tile 128x128, 8 warps (warp 32x64), 3-stage cp.async, K=256 fixed.
// All inputs PRE-ROUNDED to tf32. TRANSB path uses ldmatrix.
struct GemmP { const float* A; const float* B; const float* bias;
               float* C; float* C2; int N; int ldc; };
struct GemmBatch { GemmP p[4]; };

#define AP 36      // A smem pitch (floats) = 9 x 16B units per m-row
#define BPT 36     // B smem pitch (TRANSB)
#define BPN 136    // B smem pitch (non-T)
#define A_STG (128 * AP)
#define BT_STG (128 * BPT)
#define BN_STG (32 * BPN)
#define STG_T (A_STG + BT_STG)
#define STG_N (A_STG + BN_STG)
#define SMEM_GEMM_T (3 * STG_T * 4)
#define SMEM_GEMM_N (3 * STG_N * 4)

template <bool TRANSB, bool RELU>
__global__ __launch_bounds__(256, 2)
void gemm_tf32_kernel(GemmBatch args)
{
    const GemmP p = args.p[blockIdx.z];
    const int n0 = blockIdx.x * 128;
    if (n0 >= p.N) return;
    const int m0 = blockIdx.y * 128;

    extern __shared__ float smf[];
    const int STG = TRANSB ? STG_T : STG_N;

    const int tid  = threadIdx.x;
    const int wid  = tid >> 5;
    const int lane = tid & 31;
    const int g    = lane >> 2;
    const int c    = lane & 3;
    const int warp_m = wid >> 1;   // 0..3
    const int warp_n = wid & 1;    // 0..1

    const float* A = p.A;
    const float* B = p.B;

    auto issue = [&](int k0, float* base) {
        float* Ad = base;
        float* Bd = base + A_STG;
        #pragma unroll
        for (int it = 0; it < 4; it++) {
            const int ch = tid + it * 256;          // 1024 chunks
            const int row = ch >> 3, kq = ch & 7;
            cp_async16(Ad + row * AP + kq * 4,
                       A + (size_t)(m0 + row) * 256 + k0 + kq * 4);
        }
        if (TRANSB) {
            #pragma unroll
            for (int it = 0; it < 4; it++) {
                const int ch = tid + it * 256;
                const int row = ch >> 3, kq = ch & 7;
                cp_async16(Bd + row * BPT + kq * 4,
                           B + (size_t)(n0 + row) * 256 + k0 + kq * 4);
            }
        } else {
            #pragma unroll
            for (int it = 0; it < 4; it++) {
                const int ch = tid + it * 256;
                const int row = ch >> 5, nq = ch & 31;
                cp_async16(Bd + row * BPN + nq * 4,
                           B + (size_t)(k0 + row) * 256 + n0 + nq * 4);
            }
        }
    };

    const int r8  = lane & 7;
    const int sel = lane >> 3;
    uint32_t offA[2];
    #pragma unroll
    for (int mt = 0; mt < 2; mt++)
        offA[mt] = ((warp_m * 32 + mt * 16 + r8 + (sel & 1) * 8) * 9 + (sel >> 1)) * 16;
    uint32_t offB[4];
    #pragma unroll
    for (int pp = 0; pp < 4; pp++)
        offB[pp] = ((warp_n * 64 + (2 * pp + (sel >> 1)) * 8 + r8) * 9 + (sel & 1)) * 16;

    float acc[2][8][4];
    #pragma unroll
    for (int i = 0; i < 2; i++)
        #pragma unroll
        for (int j = 0; j < 8; j++)
            #pragma unroll
            for (int q = 0; q < 4; q++) acc[i][j][q] = 0.0f;

    issue(0,  smf);          cp_commit();
    issue(32, smf + STG);    cp_commit();

    #pragma unroll 1
    for (int iter = 0; iter < 8; iter++) {
        float* base = smf + (iter % 3) * STG;
        if (iter < 7) cp_wait<1>(); else cp_wait<0>();
        __syncthreads();
        if (iter + 2 < 8) {
            issue((iter + 2) * 32, smf + ((iter + 2) % 3) * STG);
            cp_commit();
        }

        const uint32_t abase = (uint32_t)__cvta_generic_to_shared(base);
        const uint32_t bbase = (uint32_t)__cvta_generic_to_shared(base + A_STG);
        const float*   Bd    = base + A_STG;

        #pragma unroll
        for (int kb = 0; kb < 4; kb++) {
            const int kk = kb * 8;
            uint32_t a[2][4];
            #pragma unroll
            for (int mt = 0; mt < 2; mt++)
                ldsm_x4(a[mt][0], a[mt][1], a[mt][2], a[mt][3],
                        abase + offA[mt] + kb * 32);
            uint32_t bf[8][2];
            if (TRANSB) {
                #pragma unroll
                for (int pp = 0; pp < 4; pp++)
                    ldsm_x4(bf[2 * pp][0], bf[2 * pp][1],
                            bf[2 * pp + 1][0], bf[2 * pp + 1][1],
                            bbase + offB[pp] + kb * 32);
            } else {
                #pragma unroll
                for (int nt = 0; nt < 8; nt++) {
                    const int n = warp_n * 64 + nt * 8 + g;
                    bf[nt][0] = __float_as_uint(Bd[(kk + c) * BPN + n]);
                    bf[nt][1] = __float_as_uint(Bd[(kk + c + 4) * BPN + n]);
                }
            }
            #pragma unroll
            for (int mt = 0; mt < 2; mt++)
                #pragma unroll
                for (int nt = 0; nt < 8; nt++)
                    mma_tf32(acc[mt][nt], a[mt], bf[nt]);
        }
        __syncthreads();
    }

    #pragma unroll
    for (int mt = 0; mt < 2; mt++) {
        const int r0 = m0 + warp_m * 32 + mt * 16 + g;
        #pragma unroll
        for (int nt = 0; nt < 8; nt++) {
            const int col = n0 + warp_n * 64 + nt * 8 + 2 * c;
            float2 bv = make_float2(0.f, 0.f);
            if (p.bias) bv = *(const float2*)(p.bias + col);
            float2 v0 = make_float2(acc[mt][nt][0] + bv.x, acc[mt][nt][1] + bv.y);
            float2 v1 = make_float2(acc[mt][nt][2] + bv.x, acc[mt][nt][3] + bv.y);
            if (RELU) {
                v0.x = fmaxf(v0.x, 0.f); v0.y = fmaxf(v0.y, 0.f);
                v1.x = fmaxf(v1.x, 0.f); v1.y = fmaxf(v1.y, 0.f);
            }
            *(float2*)(p.C + (size_t)r0 * p.ldc + col)       = v0;
            *(float2*)(p.C + (size_t)(r0 + 8) * p.ldc + col) = v1;
            if (p.C2) {
                float2 w0 = make_float2(round_tf32(v0.x), round_tf32(v0.y));
                float2 w1v = make_float2(round_tf32(v1.x), round_tf32(v1.y));
                *(float2*)(p.C2 + (size_t)r0 * p.ldc + col)       = w0;
                *(float2*)(p.C2 + (size_t)(r0 + 8) * p.ldc + col) = w1v;
            }
        }
    }
}

// ======================= fused attention (scores+softmax+AV) ======================
// Mask applied SPARSELY: scatter-add compact edge values into S (smem).
#define SS_PITCH 516
#define KP 36
#define VP 40
#define Q_PITCH  36
#define FA_SMEM_FLOATS (64 * SS_PITCH + 512 * VP + 64 * Q_PITCH)
#define FA_SMEM_BYTES  (FA_SMEM_FLOATS * 4)

__global__ __launch_bounds__(512)
void fused_attn_kernel(const float* __restrict__ qkvA, const float* __restrict__ qkvB,
                       const int* __restrict__ srcp, const int* __restrict__ dstp,
                       const float* __restrict__ eval,   // [mod][b][e] or nullptr
                       float* __restrict__ OA, float* __restrict__ OB)
{
    const int z = blockIdx.z;
    const float* qkv  = z ? qkvB  : qkvA;
    float*       O    = z ? OB    : OA;

    extern __shared__ float sm[];
    float*    Ss  = sm;
    float*    KVs = sm + 64 * SS_PITCH;
    uint32_t* Ssu = (uint32_t*)Ss;
    uint32_t* KVu = (uint32_t*)KVs;
    uint32_t* Qu  = (uint32_t*)(KVs + 512 * VP);

    const int tid = threadIdx.x, wid = tid >> 5, lane = tid & 31;
    const int g = lane >> 2, c = lane & 3;
    const int bh = blockIdx.y, b = bh >> 3, h = bh & 7;
    const int i0 = blockIdx.x * 64;

    {
        const int m = tid >> 3, dq = (tid & 7) * 4;
        float4 v = *(const float4*)(qkv + (size_t)(b * NN_ + i0 + m) * 768 + h * DHH + dq);
        Qu[m * Q_PITCH + dq + 0] = f32_to_tf32(v.x);
        Qu[m * Q_PITCH + dq + 1] = f32_to_tf32(v.y);
        Qu[m * Q_PITCH + dq + 2] = f32_to_tf32(v.z);
        Qu[m * Q_PITCH + dq + 3] = f32_to_tf32(v.w);
    }
    #pragma unroll
    for (int it = 0; it < 8; it++) {
        const int f = tid + it * 512;
        const int j = f >> 3, dq = (f & 7) * 4;
        float4 v = *(const float4*)(qkv + (size_t)(b * NN_ + j) * 768 + 256 + h * DHH + dq);
        KVu[j * KP + dq + 0] = f32_to_tf32(v.x);
        KVu[j * KP + dq + 1] = f32_to_tf32(v.y);
        KVu[j * KP + dq + 2] = f32_to_tf32(v.z);
        KVu[j * KP + dq + 3] = f32_to_tf32(v.w);
    }
    __syncthreads();

    // ---- phase 1: S = Q K^T, warp w owns 32-col j-slab ----
    const int jb = wid * 32;
    float acc[4][4][4];
    #pragma unroll
    for (int mt = 0; mt < 4; mt++)
        #pragma unroll
        for (int nt = 0; nt < 4; nt++)
            #pragma unroll
            for (int q = 0; q < 4; q++) acc[mt][nt][q] = 0.0f;

    #pragma unroll
    for (int kb = 0; kb < 4; kb++) {
        const int kk = kb * 8;
        uint32_t a[4][4];
        #pragma unroll
        for (int mt = 0; mt < 4; mt++) {
            const int m = mt * 16 + g;
            a[mt][0] = Qu[m * Q_PITCH + kk + c];
            a[mt][1] = Qu[(m + 8) * Q_PITCH + kk + c];
            a[mt][2] = Qu[m * Q_PITCH + kk + c + 4];
            a[mt][3] = Qu[(m + 8) * Q_PITCH + kk + c + 4];
        }
        uint32_t bf[4][2];
        #pragma unroll
        for (int nt = 0; nt < 4; nt++) {
            const int j = jb + nt * 8 + g;
            bf[nt][0] = KVu[j * KP + kk + c];
            bf[nt][1] = KVu[j * KP + kk + c + 4];
        }
        #pragma unroll
        for (int mt = 0; mt < 4; mt++)
            #pragma unroll
            for (int nt = 0; nt < 4; nt++)
                mma_tf32(acc[mt][nt], a[mt], bf[nt]);
    }

    const float scale = 0.17677669529663687f;   // 1/sqrt(32)
    #pragma unroll
    for (int mt = 0; mt < 4; mt++) {
        const int r0 = mt * 16 + g;
        #pragma unroll
        for (int nt = 0; nt < 4; nt++) {
            const int col = jb + nt * 8 + 2 * c;
            Ss[r0 * SS_PITCH + col]           = acc[mt][nt][0] * scale;
            Ss[r0 * SS_PITCH + col + 1]       = acc[mt][nt][1] * scale;
            Ss[(r0 + 8) * SS_PITCH + col]     = acc[mt][nt][2] * scale;
            Ss[(r0 + 8) * SS_PITCH + col + 1] = acc[mt][nt][3] * scale;
        }
    }
    __syncthreads();   // S complete; K reads done

    // ---- sparse mask scatter-add (unique (s,d) per b -> race-free) ----
    if (eval) {
        const int off = g_eoff[blockIdx.x * 64];
        const int cnt = g_eoff[blockIdx.x * 64 + 64] - off;
        for (int t = tid; t < cnt; t += 512) {
            const int e = g_elist[off + t];
            const int s = srcp[e];
            const int d = dstp[e];
            const float v = eval[((size_t)z * BB + b) * EE + e];
            Ss[(s - i0) * SS_PITCH + d] += v;
        }
    }

    // ---- load V (512x32, tf32, pitch 40) ----
    #pragma unroll
    for (int it = 0; it < 8; it++) {
        const int f = tid + it * 512;
        const int j = f >> 3, dq = (f & 7) * 4;
        float4 v = *(const float4*)(qkv + (size_t)(b * NN_ + j) * 768 + 512 + h * DHH + dq);
        KVu[j * VP + dq + 0] = f32_to_tf32(v.x);
        KVu[j * VP + dq + 1] = f32_to_tf32(v.y);
        KVu[j * VP + dq + 2] = f32_to_tf32(v.z);
        KVu[j * VP + dq + 3] = f32_to_tf32(v.w);
    }
    __syncthreads();   // scatter + V complete

    // ---- softmax: warp handles rows [wid*4, wid*4+4) ----
    #pragma unroll
    for (int rr = 0; rr < 4; rr++) {
        const int row = wid * 4 + rr;
        float v[16];
        float mx = -1e30f;
        #pragma unroll
        for (int t = 0; t < 16; t++) {
            v[t] = Ss[row * SS_PITCH + lane + t * 32];
            mx = fmaxf(mx, v[t]);
        }
        #pragma unroll
        for (int o = 16; o > 0; o >>= 1) mx = fmaxf(mx, __shfl_xor_sync(0xffffffffu, mx, o));
        float s = 0.0f;
        #pragma unroll
        for (int t = 0; t < 16; t++) { v[t] = __expf(v[t] - mx); s += v[t]; }
        #pragma unroll
        for (int o = 16; o > 0; o >>= 1) s += __shfl_xor_sync(0xffffffffu, s, o);
        const float inv = 1.0f / s;
        #pragma unroll
        for (int t = 0; t < 16; t++)
            Ssu[row * SS_PITCH + lane + t * 32] = f32_to_tf32(v[t] * inv);
    }
    __syncthreads();   // P (tf32) + V ready

    // ---- phase 2: O = P V, 4 independent k-chains ----
    const int mt2 = wid >> 2;
    const int nb  = (wid & 3) * 8;
    float o4[4][4] = {};
    const int m = mt2 * 16 + g;
    #pragma unroll 4
    for (int ks = 0; ks < 16; ks++) {
        #pragma unroll
        for (int q = 0; q < 4; q++) {
            const int kk = (q * 16 + ks) * 8;
            uint32_t a[4];
            a[0] = Ssu[m * SS_PITCH + kk + c];
            a[1] = Ssu[(m + 8) * SS_PITCH + kk + c];
            a[2] = Ssu[m * SS_PITCH + kk + c + 4];
            a[3] = Ssu[(m + 8) * SS_PITCH + kk + c + 4];
            uint32_t bb[2];
            bb[0] = KVu[(kk + c) * VP + nb + g];
            bb[1] = KVu[(kk + c + 4) * VP + nb + g];
            mma_tf32(o4[q], a, bb);
        }
    }
    float of[4];
    #pragma unroll
    for (int i = 0; i < 4; i++)
        of[i] = (o4[0][i] + o4[1][i]) + (o4[2][i] + o4[3][i]);

    const int r = b * NN_ + i0 + mt2 * 16 + g;
    const int colb = h * DHH + nb + 2 * c;
    *(float2*)(O + (size_t)r * DD + colb) =
        make_float2(round_tf32(of[0]), round_tf32(of[1]));
    *(float2*)(O + (size_t)(r + 8) * DD + colb) =
        make_float2(round_tf32(of[2]), round_tf32(of[3]));
}

// -------------------- edge MLP: per-edge parallel, src-sorted order ----------------
// 8 edges per warp (ILP-2 pairs), edges taken from g_elist (sorted by src) so a
// warp's G1[src] loads hit L1/registers; w2 cached in registers.
__global__ __launch_bounds__(256)
void edge_kernel(const float* __restrict__ G1a, const float* __restrict__ G2a,
                 const float* __restrict__ G1b, const float* __restrict__ G2b,
                 const int* __restrict__ src, const int* __restrict__ dst,
                 const float* __restrict__ w2, const float* __restrict__ b2,
                 float* __restrict__ Wa, float* __restrict__ Wb,
                 float* __restrict__ eval)
{
    const int z = blockIdx.z;
    const float* G1 = z ? G1b : G1a;
    const float* G2 = z ? G2b : G2a;
    float*       W  = z ? Wb  : Wa;
    const int b = blockIdx.y;
    const int wid = threadIdx.x >> 5, lane = threadIdx.x & 31;

    float4 wv0 = *(const float4*)(w2 + lane * 8);
    float4 wv1 = *(const float4*)(w2 + lane * 8 + 4);
    const float bias = b2[0];
    const int e0 = blockIdx.x * 64 + wid * 8;
    float* evz = eval + ((size_t)z * BB + b) * EE;

    #pragma unroll 1
    for (int i = 0; i < 8; i += 2) {
        const int eA = g_elist[e0 + i];
        const int eB = g_elist[e0 + i + 1];
        const int sA = src[eA], dA = dst[eA];
        const int sB = src[eB], dB = dst[eB];
        const float* g1A = G1 + ((size_t)b * NN_ + sA) * DD + lane * 8;
        const float* g2A = G2 + ((size_t)b * NN_ + dA) * DD + lane * 8;
        const float* g1B = G1 + ((size_t)b * NN_ + sB) * DD + lane * 8;
        const float* g2B = G2 + ((size_t)b * NN_ + dB) * DD + lane * 8;
        float4 a0A = *(const float4*)(g1A);
        float4 a1A = *(const float4*)(g1A + 4);
        float4 c0A = *(const float4*)(g2A);
        float4 c1A = *(const float4*)(g2A + 4);
        float4 a0B = *(const float4*)(g1B);
        float4 a1B = *(const float4*)(g1B + 4);
        float4 c0B = *(const float4*)(g2B);
        float4 c1B = *(const float4*)(g2B + 4);
        float accA = fmaxf(a0A.x + c0A.x, 0.f) * wv0.x + fmaxf(a0A.y + c0A.y, 0.f) * wv0.y
                   + fmaxf(a0A.z + c0A.z, 0.f) * wv0.z + fmaxf(a0A.w + c0A.w, 0.f) * wv0.w
                   + fmaxf(a1A.x + c1A.x, 0.f) * wv1.x + fmaxf(a1A.y + c1A.y, 0.f) * wv1.y
                   + fmaxf(a1A.z + c1A.z, 0.f) * wv1.z + fmaxf(a1A.w + c1A.w, 0.f) * wv1.w;
        float accB = fmaxf(a0B.x + c0B.x, 0.f) * wv0.x + fmaxf(a0B.y + c0B.y, 0.f) * wv0.y
                   + fmaxf(a0B.z + c0B.z, 0.f) * wv0.z + fmaxf(a0B.w + c0B.w, 0.f) * wv0.w
                   + fmaxf(a1B.x + c1B.x, 0.f) * wv1.x + fmaxf(a1B.y + c1B.y, 0.f) * wv1.y
                   + fmaxf(a1B.z + c1B.z, 0.f) * wv1.z + fmaxf(a1B.w + c1B.w, 0.f) * wv1.w;
        #pragma unroll
        for (int o = 16; o > 0; o >>= 1) {
            accA += __shfl_xor_sync(0xffffffffu, accA, o);
            accB += __shfl_xor_sync(0xffffffffu, accB, o);
        }
        if (lane == 0) {
            const float vA = 1.0f / (1.0f + __expf(-(accA + bias)));
            const float vB = 1.0f / (1.0f + __expf(-(accB + bias)));
            W[((size_t)b * NN_ + sA) * NN_ + dA] = vA;
            W[((size_t)b * NN_ + sB) * NN_ + dB] = vB;
            evz[eA] = vA;
            evz[eB] = vB;
        }
    }
}

// -------------------- consistency reduce: sigmoid(H . cw2 + cb2), batched ---------
__global__ __launch_bounds__(256)
void cons_reduce_kernel(const float* __restrict__ H0, const float* __restrict__ H1,
                        const float* __restrict__ cw2, const float* __restrict__ cb2,
                        float* __restrict__ o0, float* __restrict__ o1)
{
    const float* Hbuf = blockIdx.y ? H1 : H0;
    float* out        = blockIdx.y ? o1 : o0;
    __shared__ float red[256];
    const int row = blockIdx.x;
    const int t = threadIdx.x;
    red[t] = Hbuf[(size_t)row * DD + t] * __ldg(cw2 + t);
    __syncthreads();
    for (int s = 128; s > 0; s >>= 1) { if (t < s) red[t] += red[t + s]; __syncthreads(); }
    if (t == 0) out[row] = 1.0f / (1.0f + __expf(-(red[0] + cb2[0])));
}

// ===================================================================================
extern "C" void kernel_launch(void* const* d_in, const int* in_sizes, int n_in,
                              void* d_out, int out_size)
{
    const float* img   = (const float*)d_in[0];
    const float* txt   = (const float*)d_in[1];
    const int*   src   = (const int*)d_in[2];
    const int*   dst   = (const int*)d_in[3];
    const float* w1    = (const float*)d_in[4];
    const float* b1    = (const float*)d_in[5];
    const float* w2    = (const float*)d_in[6];
    const float* b2    = (const float*)d_in[7];
    const float* in_w  = (const float*)d_in[8];
    const float* in_b  = (const float*)d_in[9];
    const float* out_w = (const float*)d_in[10];
    const float* out_b = (const float*)d_in[11];
    const float* cw1   = (const float*)d_in[12];
    const float* cb1   = (const float*)d_in[13];
    const float* cw2   = (const float*)d_in[14];
    const float* cb2   = (const float*)d_in[15];
    float* out = (float*)d_out;

    float *qkv0, *qkv1, *attn0, *attn1, *G1i, *G2i, *G1t, *G2t, *H0, *H1;
    float *imgR, *txtR, *w1R, *inwR, *outwR, *cw1R, *aimgR, *atxtR, *evalp;
    cudaGetSymbolAddress((void**)&qkv0,  g_qkv0);
    cudaGetSymbolAddress((void**)&qkv1,  g_qkv1);
    cudaGetSymbolAddress((void**)&attn0, g_attn0);
    cudaGetSymbolAddress((void**)&attn1, g_attn1);
    cudaGetSymbolAddress((void**)&G1i,   g_G1i);
    cudaGetSymbolAddress((void**)&G2i,   g_G2i);
    cudaGetSymbolAddress((void**)&G1t,   g_G1t);
    cudaGetSymbolAddress((void**)&G2t,   g_G2t);
    cudaGetSymbolAddress((void**)&H0,    g_H0);
    cudaGetSymbolAddress((void**)&H1,    g_H1);
    cudaGetSymbolAddress((void**)&imgR,  g_imgR);
    cudaGetSymbolAddress((void**)&txtR,  g_txtR);
    cudaGetSymbolAddress((void**)&w1R,   g_w1R);
    cudaGetSymbolAddress((void**)&inwR,  g_inwR);
    cudaGetSymbolAddress((void**)&outwR, g_outwR);
    cudaGetSymbolAddress((void**)&cw1R,  g_cw1R);
    cudaGetSymbolAddress((void**)&aimgR, g_aimgR);
    cudaGetSymbolAddress((void**)&atxtR, g_atxtR);
    cudaGetSymbolAddress((void**)&evalp, g_eval);

    cudaFuncSetAttribute(fused_attn_kernel,
                         cudaFuncAttributeMaxDynamicSharedMemorySize, FA_SMEM_BYTES);
    cudaFuncSetAttribute(gemm_tf32_kernel<true, false>,
                         cudaFuncAttributeMaxDynamicSharedMemorySize, SMEM_GEMM_T);
    cudaFuncSetAttribute(gemm_tf32_kernel<false, false>,
                         cudaFuncAttributeMaxDynamicSharedMemorySize, SMEM_GEMM_N);
    cudaFuncSetAttribute(gemm_tf32_kernel<false, true>,
                         cudaFuncAttributeMaxDynamicSharedMemorySize, SMEM_GEMM_N);

    const dim3 blk(256);
    const dim3 blkfa(512);

    // ---- zero the two adjacency-weight output blocks ----
    cudaMemsetAsync(out + O_IW, 0, (size_t)2 * BB * NN_ * NN_ * sizeof(float), 0);

    // ---- pre-round all static GEMM inputs to tf32 ----
    {
        RoundBatch rb;
        rb.s[0] = img;   rb.d[0] = imgR;  rb.n[0] = BN * DD;
        rb.s[1] = txt;   rb.d[1] = txtR;  rb.n[1] = BN * DD;
        rb.s[2] = w1;    rb.d[2] = w1R;   rb.n[2] = 512 * 256;
        rb.s[3] = in_w;  rb.d[3] = inwR;  rb.n[3] = 768 * 256;
        rb.s[4] = out_w; rb.d[4] = outwR; rb.n[4] = 256 * 256;
        rb.s[5] = cw1;   rb.d[5] = cw1R;  rb.n[5] = 256 * 256;
        round_kernel<<<dim3(512, 6), blk>>>(rb);
    }
    // ---- bucket edges by exact src ----
    bucket_kernel<<<1, 512>>>(src);

    // ---- causal-weight node projections: 4 batched GEMMs ----
    {
        GemmBatch gb;
        gb.p[0] = { imgR, w1R,             b1,      G1i, nullptr, 256, 256 };
        gb.p[1] = { imgR, w1R + 256 * 256, nullptr, G2i, nullptr, 256, 256 };
        gb.p[2] = { txtR, w1R,             b1,      G1t, nullptr, 256, 256 };
        gb.p[3] = { txtR, w1R + 256 * 256, nullptr, G2t, nullptr, 256, 256 };
        gemm_tf32_kernel<false, false><<<dim3(2, 64, 4), blk, SMEM_GEMM_N>>>(gb);
    }
    edge_kernel<<<dim3(EE / 64, BB, 2), blk>>>(G1i, G2i, G1t, G2t, src, dst, w2, b2,
                                               out + O_IW, out + O_TW, evalp);

    // ---- qkv projections for MHA1+MHA2 ----
    {
        GemmBatch gb;
        gb.p[0] = { imgR, inwR, in_b, qkv0, nullptr, 768, 768 };
        gb.p[1] = { txtR, inwR, in_b, qkv1, nullptr, 768, 768 };
        gb.p[2] = gb.p[0]; gb.p[3] = gb.p[0];
        gemm_tf32_kernel<true, false><<<dim3(6, 64, 2), blk, SMEM_GEMM_T>>>(gb);
    }
    // ---- fused attention MHA1+MHA2 (sparse mask) ----
    fused_attn_kernel<<<dim3(8, 128, 2), blkfa, FA_SMEM_BYTES>>>(
        qkv0, qkv1, src, dst, evalp, attn0, attn1);
    // ---- out-proj MHA1+MHA2 (also emits tf32-rounded copies) ----
    {
        GemmBatch gb;
        gb.p[0] = { attn0, outwR, out_b, out + O_AIMG, aimgR, 256, 256 };
        gb.p[1] = { attn1, outwR, out_b, out + O_ATXT, atxtR, 256, 256 };
        gb.p[2] = gb.p[0]; gb.p[3] = gb.p[0];
        gemm_tf32_kernel<true, false><<<dim3(2, 64, 2), blk, SMEM_GEMM_T>>>(gb);
    }

    // ---- consistency heads ----
    {
        GemmBatch gb;
        gb.p[0] = { aimgR, cw1R, cb1, H0, nullptr, 256, 256 };
        gb.p[1] = { atxtR, cw1R, cb1, H1, nullptr, 256, 256 };
        gb.p[2] = gb.p[0]; gb.p[3] = gb.p[0];
        gemm_tf32_kernel<false, true><<<dim3(2, 64, 2), blk, SMEM_GEMM_N>>>(gb);
    }
    cons_reduce_kernel<<<dim3(BN, 2), blk>>>(H0, H1, cw2, cb2, out + O_IC, out + O_TC);

    // ---- MHA3 projections: q from attended_img; k|v from attended_text ----
    {
        GemmBatch gb;
        gb.p[0] = { aimgR, inwR,             in_b,       qkv0,       nullptr, 256, 768 };
        gb.p[1] = { atxtR, inwR + 256 * 256, in_b + 256, qkv0 + 256, nullptr, 512, 768 };
        gb.p[2] = gb.p[0]; gb.p[3] = gb.p[0];
        gemm_tf32_kernel<true, false><<<dim3(4, 64, 2), blk, SMEM_GEMM_T>>>(gb);
    }
    fused_attn_kernel<<<dim3(8, 128, 1), blkfa, FA_SMEM_BYTES>>>(
        qkv0, qkv0, src, dst, nullptr, attn0, attn0);
    {
        GemmBatch gb;
        gb.p[0] = { attn0, outwR, out_b, out + O_XMOD, nullptr, 256, 256 };
        gb.p[1] = gb.p[0]; gb.p[2] = gb.p[0]; gb.p[3] = gb.p[0];
        gemm_tf32_kernel<true, false><<<dim3(2, 64, 1), blk, SMEM_GEMM_T>>>(gb);
    }
}

// round 15
// speedup vs baseline: 1.1285x; 1.1285x over previous
#include <cuda_runtime.h>
#include <cuda_bf16.h>
#include <cstdint>
#include <cstddef>

// Problem constants
#define BB 16
#define NN_ 512
#define DD 256
#define HH 8
#define DHH 32
#define EE 16384
#define BN (BB * NN_)          // 8192

// Output layout (flattened tuple, in reference return order)
#define O_AIMG 0
#define O_ATXT 2097152
#define O_XMOD 4194304
#define O_IW   6291456
#define O_TW   10485760
#define O_IC   14680064
#define O_TC   14688256

// -------------------- static scratch (no allocations allowed) --------------------
__device__ float g_qkv0[BN * 768];
__device__ float g_qkv1[BN * 768];
__device__ float g_attn0[BN * DD];   // fa writes tf32-rounded
__device__ float g_attn1[BN * DD];
__device__ float g_G1i[BN * DD];
__device__ float g_G2i[BN * DD];
__device__ float g_G1t[BN * DD];
__device__ float g_G2t[BN * DD];
__device__ float g_H0[BN * DD];
__device__ float g_H1[BN * DD];
// tf32-pre-rounded copies of GEMM inputs
__device__ float g_imgR[BN * DD];
__device__ float g_txtR[BN * DD];
__device__ float g_w1R[512 * 256];
__device__ float g_inwR[768 * 256];
__device__ float g_outwR[256 * 256];
__device__ float g_cw1R[256 * 256];
__device__ float g_aimgR[BN * DD];
__device__ float g_atxtR[BN * DD];
// sparse-mask support
__device__ float g_eval[2 * BB * EE];   // compact edge values [mod][b][e]
__device__ int   g_eoff[9];             // bucket offsets by i-tile (s>>6)
__device__ int   g_elist[EE];           // edge ids sorted by bucket

__device__ __forceinline__ uint32_t f32_to_tf32(float x) {
    uint32_t r;
    asm("cvt.rna.tf32.f32 %0, %1;" : "=r"(r) : "f"(x));
    return r;
}
__device__ __forceinline__ float round_tf32(float x) {
    return __uint_as_float(f32_to_tf32(x));
}

__device__ __forceinline__ void mma_tf32(float* d, const uint32_t* a, const uint32_t* b) {
    asm volatile(
        "mma.sync.aligned.m16n8k8.row.col.f32.tf32.tf32.f32 "
        "{%0,%1,%2,%3}, {%4,%5,%6,%7}, {%8,%9}, {%0,%1,%2,%3};"
        : "+f"(d[0]), "+f"(d[1]), "+f"(d[2]), "+f"(d[3])
        : "r"(a[0]), "r"(a[1]), "r"(a[2]), "r"(a[3]), "r"(b[0]), "r"(b[1]));
}

__device__ __forceinline__ void ldsm_x4(uint32_t& r0, uint32_t& r1, uint32_t& r2,
                                        uint32_t& r3, uint32_t saddr) {
    asm volatile("ldmatrix.sync.aligned.m8n8.x4.shared.b16 {%0,%1,%2,%3}, [%4];"
                 : "=r"(r0), "=r"(r1), "=r"(r2), "=r"(r3) : "r"(saddr));
}

__device__ __forceinline__ void cp_async16(void* smem, const void* gmem) {
    uint32_t s = (uint32_t)__cvta_generic_to_shared(smem);
    asm volatile("cp.async.ca.shared.global [%0], [%1], 16;" :: "r"(s), "l"(gmem));
}
__device__ __forceinline__ void cp_commit() {
    asm volatile("cp.async.commit_group;");
}
template <int N>
__device__ __forceinline__ void cp_wait() {
    asm volatile("cp.async.wait_group %0;" :: "n"(N));
}

// ---------------- pre-round kernel: d[i] = tf32(s[i]) -----------------------------
struct RoundBatch { const float* s[6]; float* d[6]; int n[6]; };
__global__ __launch_bounds__(256)
void round_kernel(RoundBatch rb)
{
    const int z = blockIdx.y;
    const float* s = rb.s[z];
    float* d = rb.d[z];
    const int n4 = rb.n[z] >> 2;
    const int stride = gridDim.x * 256;
    for (int i = blockIdx.x * 256 + threadIdx.x; i < n4; i += stride) {
        float4 v = *(const float4*)(s + i * 4);
        v.x = round_tf32(v.x); v.y = round_tf32(v.y);
        v.z = round_tf32(v.z); v.w = round_tf32(v.w);
        *(float4*)(d + i * 4) = v;
    }
}

// ---------------- bucket kernel: sort edge ids by i-tile (s >> 6) -----------------
__global__ __launch_bounds__(256)
void bucket_kernel(const int* __restrict__ src)
{
    __shared__ int cnt[8];
    __shared__ int base[8];
    const int tid = threadIdx.x;
    if (tid < 8) cnt[tid] = 0;
    __syncthreads();
    for (int e = tid; e < EE; e += 256) atomicAdd(&cnt[src[e] >> 6], 1);
    __syncthreads();
    if (tid == 0) {
        int s = 0;
        for (int t = 0; t < 8; t++) { base[t] = s; g_eoff[t] = s; s += cnt[t]; }
        g_eoff[8] = s;
    }
    __syncthreads();
    for (int e = tid; e < EE; e += 256) {
        const int t = src[e] >> 6;
        const int pos = atomicAdd(&base[t], 1);
        g_elist[pos] = e;
    }
}

// ===================== batched, pipelined TF32 tensor-core GEMM ====================
// CTA tile 128x128, 8 warps (warp 32x64), 3-stage cp.async, K=256 fixed.
// All inputs PRE-ROUNDED to tf32. TRANSB path uses ldmatrix.
struct GemmP { const float* A; const float* B; const float* bias;
               float* C; float* C2; int N; int ldc; };
struct GemmBatch { GemmP p[4]; };

#define AP 36      // A smem pitch (floats) = 9 x 16B units per m-row
#define BPT 36     // B smem pitch (TRANSB)
#define BPN 136    // B smem pitch (non-T)
#define A_STG (128 * AP)
#define BT_STG (128 * BPT)
#define BN_STG (32 * BPN)
#define STG_T (A_STG + BT_STG)
#define STG_N (A_STG + BN_STG)
#define SMEM_GEMM_T (3 * STG_T * 4)
#define SMEM_GEMM_N (3 * STG_N * 4)

template <bool TRANSB, bool RELU>
__global__ __launch_bounds__(256, 2)
void gemm_tf32_kernel(GemmBatch args)
{
    const GemmP p = args.p[blockIdx.z];
    const int n0 = blockIdx.x * 128;
    if (n0 >= p.N) return;
    const int m0 = blockIdx.y * 128;

    extern __shared__ float smf[];
    const int STG = TRANSB ? STG_T : STG_N;

    const int tid  = threadIdx.x;
    const int wid  = tid >> 5;
    const int lane = tid & 31;
    const int g    = lane >> 2;
    const int c    = lane & 3;
    const int warp_m = wid >> 1;   // 0..3
    const int warp_n = wid & 1;    // 0..1

    const float* A = p.A;
    const float* B = p.B;

    auto issue = [&](int k0, float* base) {
        float* Ad = base;
        float* Bd = base + A_STG;
        #pragma unroll
        for (int it = 0; it < 4; it++) {
            const int ch = tid + it * 256;          // 1024 chunks
            const int row = ch >> 3, kq = ch & 7;
            cp_async16(Ad + row * AP + kq * 4,
                       A + (size_t)(m0 + row) * 256 + k0 + kq * 4);
        }
        if (TRANSB) {
            #pragma unroll
            for (int it = 0; it < 4; it++) {
                const int ch = tid + it * 256;
                const int row = ch >> 3, kq = ch & 7;
                cp_async16(Bd + row * BPT + kq * 4,
                           B + (size_t)(n0 + row) * 256 + k0 + kq * 4);
            }
        } else {
            #pragma unroll
            for (int it = 0; it < 4; it++) {
                const int ch = tid + it * 256;
                const int row = ch >> 5, nq = ch & 31;
                cp_async16(Bd + row * BPN + nq * 4,
                           B + (size_t)(k0 + row) * 256 + n0 + nq * 4);
            }
        }
    };

    const int r8  = lane & 7;
    const int sel = lane >> 3;
    uint32_t offA[2];
    #pragma unroll
    for (int mt = 0; mt < 2; mt++)
        offA[mt] = ((warp_m * 32 + mt * 16 + r8 + (sel & 1) * 8) * 9 + (sel >> 1)) * 16;
    uint32_t offB[4];
    #pragma unroll
    for (int pp = 0; pp < 4; pp++)
        offB[pp] = ((warp_n * 64 + (2 * pp + (sel >> 1)) * 8 + r8) * 9 + (sel & 1)) * 16;

    float acc[2][8][4];
    #pragma unroll
    for (int i = 0; i < 2; i++)
        #pragma unroll
        for (int j = 0; j < 8; j++)
            #pragma unroll
            for (int q = 0; q < 4; q++) acc[i][j][q] = 0.0f;

    issue(0,  smf);          cp_commit();
    issue(32, smf + STG);    cp_commit();

    #pragma unroll 1
    for (int iter = 0; iter < 8; iter++) {
        float* base = smf + (iter % 3) * STG;
        if (iter < 7) cp_wait<1>(); else cp_wait<0>();
        __syncthreads();
        if (iter + 2 < 8) {
            issue((iter + 2) * 32, smf + ((iter + 2) % 3) * STG);
            cp_commit();
        }

        const uint32_t abase = (uint32_t)__cvta_generic_to_shared(base);
        const uint32_t bbase = (uint32_t)__cvta_generic_to_shared(base + A_STG);
        const float*   Bd    = base + A_STG;

        #pragma unroll
        for (int kb = 0; kb < 4; kb++) {
            const int kk = kb * 8;
            uint32_t a[2][4];
            #pragma unroll
            for (int mt = 0; mt < 2; mt++)
                ldsm_x4(a[mt][0], a[mt][1], a[mt][2], a[mt][3],
                        abase + offA[mt] + kb * 32);
            uint32_t bf[8][2];
            if (TRANSB) {
                #pragma unroll
                for (int pp = 0; pp < 4; pp++)
                    ldsm_x4(bf[2 * pp][0], bf[2 * pp][1],
                            bf[2 * pp + 1][0], bf[2 * pp + 1][1],
                            bbase + offB[pp] + kb * 32);
            } else {
                #pragma unroll
                for (int nt = 0; nt < 8; nt++) {
                    const int n = warp_n * 64 + nt * 8 + g;
                    bf[nt][0] = __float_as_uint(Bd[(kk + c) * BPN + n]);
                    bf[nt][1] = __float_as_uint(Bd[(kk + c + 4) * BPN + n]);
                }
            }
            #pragma unroll
            for (int mt = 0; mt < 2; mt++)
                #pragma unroll
                for (int nt = 0; nt < 8; nt++)
                    mma_tf32(acc[mt][nt], a[mt], bf[nt]);
        }
        __syncthreads();
    }

    #pragma unroll
    for (int mt = 0; mt < 2; mt++) {
        const int r0 = m0 + warp_m * 32 + mt * 16 + g;
        #pragma unroll
        for (int nt = 0; nt < 8; nt++) {
            const int col = n0 + warp_n * 64 + nt * 8 + 2 * c;
            float2 bv = make_float2(0.f, 0.f);
            if (p.bias) bv = *(const float2*)(p.bias + col);
            float2 v0 = make_float2(acc[mt][nt][0] + bv.x, acc[mt][nt][1] + bv.y);
            float2 v1 = make_float2(acc[mt][nt][2] + bv.x, acc[mt][nt][3] + bv.y);
            if (RELU) {
                v0.x = fmaxf(v0.x, 0.f); v0.y = fmaxf(v0.y, 0.f);
                v1.x = fmaxf(v1.x, 0.f); v1.y = fmaxf(v1.y, 0.f);
            }
            *(float2*)(p.C + (size_t)r0 * p.ldc + col)       = v0;
            *(float2*)(p.C + (size_t)(r0 + 8) * p.ldc + col) = v1;
            if (p.C2) {
                float2 w0 = make_float2(round_tf32(v0.x), round_tf32(v0.y));
                float2 w1v = make_float2(round_tf32(v1.x), round_tf32(v1.y));
                *(float2*)(p.C2 + (size_t)r0 * p.ldc + col)       = w0;
                *(float2*)(p.C2 + (size_t)(r0 + 8) * p.ldc + col) = w1v;
            }
        }
    }
}

// ======================= fused attention (scores+softmax+AV) ======================
// Mask applied SPARSELY: scatter-add compact edge values into S (smem).
#define SS_PITCH 516
#define KP 36
#define VP 40
#define Q_PITCH  36
#define FA_SMEM_FLOATS (64 * SS_PITCH + 512 * VP + 64 * Q_PITCH)
#define FA_SMEM_BYTES  (FA_SMEM_FLOATS * 4)

__global__ __launch_bounds__(512)
void fused_attn_kernel(const float* __restrict__ qkvA, const float* __restrict__ qkvB,
                       const int* __restrict__ srcp, const int* __restrict__ dstp,
                       const float* __restrict__ eval,   // [mod][b][e] or nullptr
                       float* __restrict__ OA, float* __restrict__ OB)
{
    const int z = blockIdx.z;
    const float* qkv  = z ? qkvB  : qkvA;
    float*       O    = z ? OB    : OA;

    extern __shared__ float sm[];
    float*    Ss  = sm;
    float*    KVs = sm + 64 * SS_PITCH;
    uint32_t* Ssu = (uint32_t*)Ss;
    uint32_t* KVu = (uint32_t*)KVs;
    uint32_t* Qu  = (uint32_t*)(KVs + 512 * VP);

    const int tid = threadIdx.x, wid = tid >> 5, lane = tid & 31;
    const int g = lane >> 2, c = lane & 3;
    const int bh = blockIdx.y, b = bh >> 3, h = bh & 7;
    const int i0 = blockIdx.x * 64;

    {
        const int m = tid >> 3, dq = (tid & 7) * 4;
        float4 v = *(const float4*)(qkv + (size_t)(b * NN_ + i0 + m) * 768 + h * DHH + dq);
        Qu[m * Q_PITCH + dq + 0] = f32_to_tf32(v.x);
        Qu[m * Q_PITCH + dq + 1] = f32_to_tf32(v.y);
        Qu[m * Q_PITCH + dq + 2] = f32_to_tf32(v.z);
        Qu[m * Q_PITCH + dq + 3] = f32_to_tf32(v.w);
    }
    #pragma unroll
    for (int it = 0; it < 8; it++) {
        const int f = tid + it * 512;
        const int j = f >> 3, dq = (f & 7) * 4;
        float4 v = *(const float4*)(qkv + (size_t)(b * NN_ + j) * 768 + 256 + h * DHH + dq);
        KVu[j * KP + dq + 0] = f32_to_tf32(v.x);
        KVu[j * KP + dq + 1] = f32_to_tf32(v.y);
        KVu[j * KP + dq + 2] = f32_to_tf32(v.z);
        KVu[j * KP + dq + 3] = f32_to_tf32(v.w);
    }
    __syncthreads();

    // ---- phase 1: S = Q K^T, warp w owns 32-col j-slab ----
    const int jb = wid * 32;
    float acc[4][4][4];
    #pragma unroll
    for (int mt = 0; mt < 4; mt++)
        #pragma unroll
        for (int nt = 0; nt < 4; nt++)
            #pragma unroll
            for (int q = 0; q < 4; q++) acc[mt][nt][q] = 0.0f;

    #pragma unroll
    for (int kb = 0; kb < 4; kb++) {
        const int kk = kb * 8;
        uint32_t a[4][4];
        #pragma unroll
        for (int mt = 0; mt < 4; mt++) {
            const int m = mt * 16 + g;
            a[mt][0] = Qu[m * Q_PITCH + kk + c];
            a[mt][1] = Qu[(m + 8) * Q_PITCH + kk + c];
            a[mt][2] = Qu[m * Q_PITCH + kk + c + 4];
            a[mt][3] = Qu[(m + 8) * Q_PITCH + kk + c + 4];
        }
        uint32_t bf[4][2];
        #pragma unroll
        for (int nt = 0; nt < 4; nt++) {
            const int j = jb + nt * 8 + g;
            bf[nt][0] = KVu[j * KP + kk + c];
            bf[nt][1] = KVu[j * KP + kk + c + 4];
        }
        #pragma unroll
        for (int mt = 0; mt < 4; mt++)
            #pragma unroll
            for (int nt = 0; nt < 4; nt++)
                mma_tf32(acc[mt][nt], a[mt], bf[nt]);
    }

    const float scale = 0.17677669529663687f;   // 1/sqrt(32)
    #pragma unroll
    for (int mt = 0; mt < 4; mt++) {
        const int r0 = mt * 16 + g;
        #pragma unroll
        for (int nt = 0; nt < 4; nt++) {
            const int col = jb + nt * 8 + 2 * c;
            Ss[r0 * SS_PITCH + col]           = acc[mt][nt][0] * scale;
            Ss[r0 * SS_PITCH + col + 1]       = acc[mt][nt][1] * scale;
            Ss[(r0 + 8) * SS_PITCH + col]     = acc[mt][nt][2] * scale;
            Ss[(r0 + 8) * SS_PITCH + col + 1] = acc[mt][nt][3] * scale;
        }
    }
    __syncthreads();   // S complete; K reads done

    // ---- sparse mask scatter-add (unique (s,d) per b -> race-free) ----
    if (eval) {
        const int tile = blockIdx.x;
        const int off = g_eoff[tile];
        const int cnt = g_eoff[tile + 1] - off;
        for (int t = tid; t < cnt; t += 512) {
            const int e = g_elist[off + t];
            const int s = srcp[e];
            const int d = dstp[e];
            const float v = eval[((size_t)z * BB + b) * EE + e];
            Ss[(s - i0) * SS_PITCH + d] += v;
        }
    }

    // ---- load V (512x32, tf32, pitch 40) ----
    #pragma unroll
    for (int it = 0; it < 8; it++) {
        const int f = tid + it * 512;
        const int j = f >> 3, dq = (f & 7) * 4;
        float4 v = *(const float4*)(qkv + (size_t)(b * NN_ + j) * 768 + 512 + h * DHH + dq);
        KVu[j * VP + dq + 0] = f32_to_tf32(v.x);
        KVu[j * VP + dq + 1] = f32_to_tf32(v.y);
        KVu[j * VP + dq + 2] = f32_to_tf32(v.z);
        KVu[j * VP + dq + 3] = f32_to_tf32(v.w);
    }
    __syncthreads();   // scatter + V complete

    // ---- softmax: warp handles rows [wid*4, wid*4+4) ----
    #pragma unroll
    for (int rr = 0; rr < 4; rr++) {
        const int row = wid * 4 + rr;
        float v[16];
        float mx = -1e30f;
        #pragma unroll
        for (int t = 0; t < 16; t++) {
            v[t] = Ss[row * SS_PITCH + lane + t * 32];
            mx = fmaxf(mx, v[t]);
        }
        #pragma unroll
        for (int o = 16; o > 0; o >>= 1) mx = fmaxf(mx, __shfl_xor_sync(0xffffffffu, mx, o));
        float s = 0.0f;
        #pragma unroll
        for (int t = 0; t < 16; t++) { v[t] = __expf(v[t] - mx); s += v[t]; }
        #pragma unroll
        for (int o = 16; o > 0; o >>= 1) s += __shfl_xor_sync(0xffffffffu, s, o);
        const float inv = 1.0f / s;
        #pragma unroll
        for (int t = 0; t < 16; t++)
            Ssu[row * SS_PITCH + lane + t * 32] = f32_to_tf32(v[t] * inv);
    }
    __syncthreads();   // P (tf32) + V ready

    // ---- phase 2: O = P V, 4 independent k-chains to break MMA latency ----
    const int mt2 = wid >> 2;
    const int nb  = (wid & 3) * 8;
    float o4[4][4] = {};
    const int m = mt2 * 16 + g;
    #pragma unroll 4
    for (int ks = 0; ks < 16; ks++) {
        #pragma unroll
        for (int q = 0; q < 4; q++) {
            const int kk = (q * 16 + ks) * 8;
            uint32_t a[4];
            a[0] = Ssu[m * SS_PITCH + kk + c];
            a[1] = Ssu[(m + 8) * SS_PITCH + kk + c];
            a[2] = Ssu[m * SS_PITCH + kk + c + 4];
            a[3] = Ssu[(m + 8) * SS_PITCH + kk + c + 4];
            uint32_t bb[2];
            bb[0] = KVu[(kk + c) * VP + nb + g];
            bb[1] = KVu[(kk + c + 4) * VP + nb + g];
            mma_tf32(o4[q], a, bb);
        }
    }
    float of[4];
    #pragma unroll
    for (int i = 0; i < 4; i++)
        of[i] = (o4[0][i] + o4[1][i]) + (o4[2][i] + o4[3][i]);

    const int r = b * NN_ + i0 + mt2 * 16 + g;
    const int colb = h * DHH + nb + 2 * c;
    *(float2*)(O + (size_t)r * DD + colb) =
        make_float2(round_tf32(of[0]), round_tf32(of[1]));
    *(float2*)(O + (size_t)(r + 8) * DD + colb) =
        make_float2(round_tf32(of[2]), round_tf32(of[3]));
}

// -------------------- edge MLP: sigmoid( relu(G1[src]+G2[dst]) . w2 + b2 ) --------
// Batched (z: img/text); 8 edges per warp processed in ILP-2 pairs; w2 in registers.
// Writes dense W (output) AND compact eval[z][b][e] for the fa sparse-mask path.
__global__ __launch_bounds__(256)
void edge_kernel(const float* __restrict__ G1a, const float* __restrict__ G2a,
                 const float* __restrict__ G1b, const float* __restrict__ G2b,
                 const int* __restrict__ src, const int* __restrict__ dst,
                 const float* __restrict__ w2, const float* __restrict__ b2,
                 float* __restrict__ Wa, float* __restrict__ Wb,
                 float* __restrict__ eval)
{
    const int z = blockIdx.z;
    const float* G1 = z ? G1b : G1a;
    const float* G2 = z ? G2b : G2a;
    float*       W  = z ? Wb  : Wa;
    const int b = blockIdx.y;
    const int wid = threadIdx.x >> 5, lane = threadIdx.x & 31;

    float4 wv0 = *(const float4*)(w2 + lane * 8);
    float4 wv1 = *(const float4*)(w2 + lane * 8 + 4);
    const float bias = b2[0];
    const int e0 = blockIdx.x * 64 + wid * 8;
    float* evz = eval + ((size_t)z * BB + b) * EE;

    #pragma unroll 1
    for (int i = 0; i < 8; i += 2) {
        const int eA = e0 + i, eB = e0 + i + 1;
        const int sA = src[eA], dA = dst[eA];
        const int sB = src[eB], dB = dst[eB];
        const float* g1A = G1 + ((size_t)b * NN_ + sA) * DD + lane * 8;
        const float* g2A = G2 + ((size_t)b * NN_ + dA) * DD + lane * 8;
        const float* g1B = G1 + ((size_t)b * NN_ + sB) * DD + lane * 8;
        const float* g2B = G2 + ((size_t)b * NN_ + dB) * DD + lane * 8;
        float4 a0A = *(const float4*)(g1A);
        float4 a1A = *(const float4*)(g1A + 4);
        float4 c0A = *(const float4*)(g2A);
        float4 c1A = *(const float4*)(g2A + 4);
        float4 a0B = *(const float4*)(g1B);
        float4 a1B = *(const float4*)(g1B + 4);
        float4 c0B = *(const float4*)(g2B);
        float4 c1B = *(const float4*)(g2B + 4);
        float accA = fmaxf(a0A.x + c0A.x, 0.f) * wv0.x + fmaxf(a0A.y + c0A.y, 0.f) * wv0.y
                   + fmaxf(a0A.z + c0A.z, 0.f) * wv0.z + fmaxf(a0A.w + c0A.w, 0.f) * wv0.w
                   + fmaxf(a1A.x + c1A.x, 0.f) * wv1.x + fmaxf(a1A.y + c1A.y, 0.f) * wv1.y
                   + fmaxf(a1A.z + c1A.z, 0.f) * wv1.z + fmaxf(a1A.w + c1A.w, 0.f) * wv1.w;
        float accB = fmaxf(a0B.x + c0B.x, 0.f) * wv0.x + fmaxf(a0B.y + c0B.y, 0.f) * wv0.y
                   + fmaxf(a0B.z + c0B.z, 0.f) * wv0.z + fmaxf(a0B.w + c0B.w, 0.f) * wv0.w
                   + fmaxf(a1B.x + c1B.x, 0.f) * wv1.x + fmaxf(a1B.y + c1B.y, 0.f) * wv1.y
                   + fmaxf(a1B.z + c1B.z, 0.f) * wv1.z + fmaxf(a1B.w + c1B.w, 0.f) * wv1.w;
        #pragma unroll
        for (int o = 16; o > 0; o >>= 1) {
            accA += __shfl_xor_sync(0xffffffffu, accA, o);
            accB += __shfl_xor_sync(0xffffffffu, accB, o);
        }
        if (lane == 0) {
            const float vA = 1.0f / (1.0f + __expf(-(accA + bias)));
            const float vB = 1.0f / (1.0f + __expf(-(accB + bias)));
            W[((size_t)b * NN_ + sA) * NN_ + dA] = vA;
            W[((size_t)b * NN_ + sB) * NN_ + dB] = vB;
            evz[eA] = vA;
            evz[eB] = vB;
        }
    }
}

// -------------------- consistency reduce: sigmoid(H . cw2 + cb2), batched ---------
__global__ __launch_bounds__(256)
void cons_reduce_kernel(const float* __restrict__ H0, const float* __restrict__ H1,
                        const float* __restrict__ cw2, const float* __restrict__ cb2,
                        float* __restrict__ o0, float* __restrict__ o1)
{
    const float* Hbuf = blockIdx.y ? H1 : H0;
    float* out        = blockIdx.y ? o1 : o0;
    __shared__ float red[256];
    const int row = blockIdx.x;
    const int t = threadIdx.x;
    red[t] = Hbuf[(size_t)row * DD + t] * __ldg(cw2 + t);
    __syncthreads();
    for (int s = 128; s > 0; s >>= 1) { if (t < s) red[t] += red[t + s]; __syncthreads(); }
    if (t == 0) out[row] = 1.0f / (1.0f + __expf(-(red[0] + cb2[0])));
}

// ===================================================================================
extern "C" void kernel_launch(void* const* d_in, const int* in_sizes, int n_in,
                              void* d_out, int out_size)
{
    const float* img   = (const float*)d_in[0];
    const float* txt   = (const float*)d_in[1];
    const int*   src   = (const int*)d_in[2];
    const int*   dst   = (const int*)d_in[3];
    const float* w1    = (const float*)d_in[4];
    const float* b1    = (const float*)d_in[5];
    const float* w2    = (const float*)d_in[6];
    const float* b2    = (const float*)d_in[7];
    const float* in_w  = (const float*)d_in[8];
    const float* in_b  = (const float*)d_in[9];
    const float* out_w = (const float*)d_in[10];
    const float* out_b = (const float*)d_in[11];
    const float* cw1   = (const float*)d_in[12];
    const float* cb1   = (const float*)d_in[13];
    const float* cw2   = (const float*)d_in[14];
    const float* cb2   = (const float*)d_in[15];
    float* out = (float*)d_out;

    float *qkv0, *qkv1, *attn0, *attn1, *G1i, *G2i, *G1t, *G2t, *H0, *H1;
    float *imgR, *txtR, *w1R, *inwR, *outwR, *cw1R, *aimgR, *atxtR, *evalp;
    cudaGetSymbolAddress((void**)&qkv0,  g_qkv0);
    cudaGetSymbolAddress((void**)&qkv1,  g_qkv1);
    cudaGetSymbolAddress((void**)&attn0, g_attn0);
    cudaGetSymbolAddress((void**)&attn1, g_attn1);
    cudaGetSymbolAddress((void**)&G1i,   g_G1i);
    cudaGetSymbolAddress((void**)&G2i,   g_G2i);
    cudaGetSymbolAddress((void**)&G1t,   g_G1t);
    cudaGetSymbolAddress((void**)&G2t,   g_G2t);
    cudaGetSymbolAddress((void**)&H0,    g_H0);
    cudaGetSymbolAddress((void**)&H1,    g_H1);
    cudaGetSymbolAddress((void**)&imgR,  g_imgR);
    cudaGetSymbolAddress((void**)&txtR,  g_txtR);
    cudaGetSymbolAddress((void**)&w1R,   g_w1R);
    cudaGetSymbolAddress((void**)&inwR,  g_inwR);
    cudaGetSymbolAddress((void**)&outwR, g_outwR);
    cudaGetSymbolAddress((void**)&cw1R,  g_cw1R);
    cudaGetSymbolAddress((void**)&aimgR, g_aimgR);
    cudaGetSymbolAddress((void**)&atxtR, g_atxtR);
    cudaGetSymbolAddress((void**)&evalp, g_eval);

    cudaFuncSetAttribute(fused_attn_kernel,
                         cudaFuncAttributeMaxDynamicSharedMemorySize, FA_SMEM_BYTES);
    cudaFuncSetAttribute(gemm_tf32_kernel<true, false>,
                         cudaFuncAttributeMaxDynamicSharedMemorySize, SMEM_GEMM_T);
    cudaFuncSetAttribute(gemm_tf32_kernel<false, false>,
                         cudaFuncAttributeMaxDynamicSharedMemorySize, SMEM_GEMM_N);
    cudaFuncSetAttribute(gemm_tf32_kernel<false, true>,
                         cudaFuncAttributeMaxDynamicSharedMemorySize, SMEM_GEMM_N);

    const dim3 blk(256);
    const dim3 blkfa(512);

    // ---- zero the two adjacency-weight output blocks (async memset: capture-legal)
    cudaMemsetAsync(out + O_IW, 0, (size_t)2 * BB * NN_ * NN_ * sizeof(float), 0);

    // ---- pre-round all static GEMM inputs to tf32 ----
    {
        RoundBatch rb;
        rb.s[0] = img;   rb.d[0] = imgR;  rb.n[0] = BN * DD;
        rb.s[1] = txt;   rb.d[1] = txtR;  rb.n[1] = BN * DD;
        rb.s[2] = w1;    rb.d[2] = w1R;   rb.n[2] = 512 * 256;
        rb.s[3] = in_w;  rb.d[3] = inwR;  rb.n[3] = 768 * 256;
        rb.s[4] = out_w; rb.d[4] = outwR; rb.n[4] = 256 * 256;
        rb.s[5] = cw1;   rb.d[5] = cw1R;  rb.n[5] = 256 * 256;
        round_kernel<<<dim3(512, 6), blk>>>(rb);
    }
    // ---- bucket edges by i-tile ----
    bucket_kernel<<<1, 256>>>(src);

    // ---- causal-weight node projections: 4 batched GEMMs ----
    {
        GemmBatch gb;
        gb.p[0] = { imgR, w1R,             b1,      G1i, nullptr, 256, 256 };
        gb.p[1] = { imgR, w1R + 256 * 256, nullptr, G2i, nullptr, 256, 256 };
        gb.p[2] = { txtR, w1R,             b1,      G1t, nullptr, 256, 256 };
        gb.p[3] = { txtR, w1R + 256 * 256, nullptr, G2t, nullptr, 256, 256 };
        gemm_tf32_kernel<false, false><<<dim3(2, 64, 4), blk, SMEM_GEMM_N>>>(gb);
    }
    edge_kernel<<<dim3(EE / 64, BB, 2), blk>>>(G1i, G2i, G1t, G2t, src, dst, w2, b2,
                                               out + O_IW, out + O_TW, evalp);

    // ---- qkv projections for MHA1+MHA2 ----
    {
        GemmBatch gb;
        gb.p[0] = { imgR, inwR, in_b, qkv0, nullptr, 768, 768 };
        gb.p[1] = { txtR, inwR, in_b, qkv1, nullptr, 768, 768 };
        gb.p[2] = gb.p[0]; gb.p[3] = gb.p[0];
        gemm_tf32_kernel<true, false><<<dim3(6, 64, 2), blk, SMEM_GEMM_T>>>(gb);
    }
    // ---- fused attention MHA1+MHA2 (sparse mask) ----
    fused_attn_kernel<<<dim3(8, 128, 2), blkfa, FA_SMEM_BYTES>>>(
        qkv0, qkv1, src, dst, evalp, attn0, attn1);
    // ---- out-proj MHA1+MHA2 (also emits tf32-rounded copies) ----
    {
        GemmBatch gb;
        gb.p[0] = { attn0, outwR, out_b, out + O_AIMG, aimgR, 256, 256 };
        gb.p[1] = { attn1, outwR, out_b, out + O_ATXT, atxtR, 256, 256 };
        gb.p[2] = gb.p[0]; gb.p[3] = gb.p[0];
        gemm_tf32_kernel<true, false><<<dim3(2, 64, 2), blk, SMEM_GEMM_T>>>(gb);
    }

    // ---- consistency heads ----
    {
        GemmBatch gb;
        gb.p[0] = { aimgR, cw1R, cb1, H0, nullptr, 256, 256 };
        gb.p[1] = { atxtR, cw1R, cb1, H1, nullptr, 256, 256 };
        gb.p[2] = gb.p[0]; gb.p[3] = gb.p[0];
        gemm_tf32_kernel<false, true><<<dim3(2, 64, 2), blk, SMEM_GEMM_N>>>(gb);
    }
    cons_reduce_kernel<<<dim3(BN, 2), blk>>>(H0, H1, cw2, cb2, out + O_IC, out + O_TC);

    // ---- MHA3 projections: q from attended_img; k|v from attended_text ----
    {
        GemmBatch gb;
        gb.p[0] = { aimgR, inwR,             in_b,       qkv0,       nullptr, 256, 768 };
        gb.p[1] = { atxtR, inwR + 256 * 256, in_b + 256, qkv0 + 256, nullptr, 512, 768 };
        gb.p[2] = gb.p[0]; gb.p[3] = gb.p[0];
        gemm_tf32_kernel<true, false><<<dim3(4, 64, 2), blk, SMEM_GEMM_T>>>(gb);
    }
    fused_attn_kernel<<<dim3(8, 128, 1), blkfa, FA_SMEM_BYTES>>>(
        qkv0, qkv0, src, dst, nullptr, attn0, attn0);
    {
        GemmBatch gb;
        gb.p[0] = { attn0, outwR, out_b, out + O_XMOD, nullptr, 256, 256 };
        gb.p[1] = gb.p[0]; gb.p[2] = gb.p[0]; gb.p[3] = gb.p[0];
        gemm_tf32_kernel<true, false><<<dim3(2, 64, 1), blk, SMEM_GEMM_T>>>(gb);
    }
}

// round 16
// speedup vs baseline: 1.1729x; 1.0394x over previous
#include <cuda_runtime.h>
#include <cuda_bf16.h>
#include <cstdint>
#include <cstddef>

// Problem constants
#define BB 16
#define NN_ 512
#define DD 256
#define HH 8
#define DHH 32
#define EE 16384
#define BN (BB * NN_)          // 8192

// Output layout (flattened tuple, in reference return order)
#define O_AIMG 0
#define O_ATXT 2097152
#define O_XMOD 4194304
#define O_IW   6291456
#define O_TW   10485760
#define O_IC   14680064
#define O_TC   14688256

// -------------------- static scratch (no allocations allowed) --------------------
__device__ float g_qkv0[BN * 768];
__device__ float g_qkv1[BN * 768];
__device__ float g_attn0[BN * DD];   // fa writes tf32-rounded
__device__ float g_attn1[BN * DD];
__device__ float g_G1i[BN * DD];
__device__ float g_G2i[BN * DD];
__device__ float g_G1t[BN * DD];
__device__ float g_G2t[BN * DD];
__device__ float g_H0[BN * DD];
__device__ float g_H1[BN * DD];
// tf32-pre-rounded copies of GEMM inputs
__device__ float g_imgR[BN * DD];
__device__ float g_txtR[BN * DD];
__device__ float g_w1R[512 * 256];
__device__ float g_inwR[768 * 256];
__device__ float g_outwR[256 * 256];
__device__ float g_cw1R[256 * 256];
__device__ float g_aimgR[BN * DD];
__device__ float g_atxtR[BN * DD];
// sparse-mask support
__device__ float g_eval[2 * BB * EE];   // compact edge values [mod][b][e]
__device__ int   g_eoff[9];             // bucket offsets by i-tile (s>>6)
__device__ int   g_elist[EE];           // edge ids sorted by bucket

__device__ __forceinline__ uint32_t f32_to_tf32(float x) {
    uint32_t r;
    asm("cvt.rna.tf32.f32 %0, %1;" : "=r"(r) : "f"(x));
    return r;
}
__device__ __forceinline__ float round_tf32(float x) {
    return __uint_as_float(f32_to_tf32(x));
}

__device__ __forceinline__ void mma_tf32(float* d, const uint32_t* a, const uint32_t* b) {
    asm volatile(
        "mma.sync.aligned.m16n8k8.row.col.f32.tf32.tf32.f32 "
        "{%0,%1,%2,%3}, {%4,%5,%6,%7}, {%8,%9}, {%0,%1,%2,%3};"
        : "+f"(d[0]), "+f"(d[1]), "+f"(d[2]), "+f"(d[3])
        : "r"(a[0]), "r"(a[1]), "r"(a[2]), "r"(a[3]), "r"(b[0]), "r"(b[1]));
}

__device__ __forceinline__ void ldsm_x4(uint32_t& r0, uint32_t& r1, uint32_t& r2,
                                        uint32_t& r3, uint32_t saddr) {
    asm volatile("ldmatrix.sync.aligned.m8n8.x4.shared.b16 {%0,%1,%2,%3}, [%4];"
                 : "=r"(r0), "=r"(r1), "=r"(r2), "=r"(r3) : "r"(saddr));
}

__device__ __forceinline__ void cp_async16(void* smem, const void* gmem) {
    uint32_t s = (uint32_t)__cvta_generic_to_shared(smem);
    asm volatile("cp.async.ca.shared.global [%0], [%1], 16;" :: "r"(s), "l"(gmem));
}
__device__ __forceinline__ void cp_commit() {
    asm volatile("cp.async.commit_group;");
}
template <int N>
__device__ __forceinline__ void cp_wait() {
    asm volatile("cp.async.wait_group %0;" :: "n"(N));
}

// ---------------- pre-round kernel: d[i] = tf32(s[i]) -----------------------------
struct RoundBatch { const float* s[6]; float* d[6]; int n[6]; };
__global__ __launch_bounds__(256)
void round_kernel(RoundBatch rb)
{
    const int z = blockIdx.y;
    const float* s = rb.s[z];
    float* d = rb.d[z];
    const int n4 = rb.n[z] >> 2;
    const int stride = gridDim.x * 256;
    for (int i = blockIdx.x * 256 + threadIdx.x; i < n4; i += stride) {
        float4 v = *(const float4*)(s + i * 4);
        v.x = round_tf32(v.x); v.y = round_tf32(v.y);
        v.z = round_tf32(v.z); v.w = round_tf32(v.w);
        *(float4*)(d + i * 4) = v;
    }
}

// ---------------- bucket kernel: sort edge ids by i-tile (s >> 6) -----------------
__global__ __launch_bounds__(256)
void bucket_kernel(const int* __restrict__ src)
{
    __shared__ int cnt[8];
    __shared__ int base[8];
    const int tid = threadIdx.x;
    if (tid < 8) cnt[tid] = 0;
    __syncthreads();
    for (int e = tid; e < EE; e += 256) atomicAdd(&cnt[src[e] >> 6], 1);
    __syncthreads();
    if (tid == 0) {
        int s = 0;
        for (int t = 0; t < 8; t++) { base[t] = s; g_eoff[t] = s; s += cnt[t]; }
        g_eoff[8] = s;
    }
    __syncthreads();
    for (int e = tid; e < EE; e += 256) {
        const int t = src[e] >> 6;
        const int pos = atomicAdd(&base[t], 1);
        g_elist[pos] = e;
    }
}

// ===================== batched, pipelined TF32 tensor-core GEMM ====================
// CTA tile 128x128, 8 warps (warp 32x64), 3-stage cp.async, K=256 fixed.
// All inputs PRE-ROUNDED to tf32. TRANSB path uses ldmatrix.
struct GemmP { const float* A; const float* B; const float* bias;
               float* C; float* C2; int N; int ldc; };
struct GemmBatch { GemmP p[4]; };

#define AP 36      // A smem pitch (floats) = 9 x 16B units per m-row
#define BPT 36     // B smem pitch (TRANSB)
#define BPN 136    // B smem pitch (non-T)
#define A_STG (128 * AP)
#define BT_STG (128 * BPT)
#define BN_STG (32 * BPN)
#define STG_T (A_STG + BT_STG)
#define STG_N (A_STG + BN_STG)
#define SMEM_GEMM_T (3 * STG_T * 4)
#define SMEM_GEMM_N (3 * STG_N * 4)

template <bool TRANSB, bool RELU>
__global__ __launch_bounds__(256, 2)
void gemm_tf32_kernel(GemmBatch args)
{
    const GemmP p = args.p[blockIdx.z];
    const int n0 = blockIdx.x * 128;
    if (n0 >= p.N) return;
    const int m0 = blockIdx.y * 128;

    extern __shared__ float smf[];
    const int STG = TRANSB ? STG_T : STG_N;

    const int tid  = threadIdx.x;
    const int wid  = tid >> 5;
    const int lane = tid & 31;
    const int g    = lane >> 2;
    const int c    = lane & 3;
    const int warp_m = wid >> 1;   // 0..3
    const int warp_n = wid & 1;    // 0..1

    const float* A = p.A;
    const float* B = p.B;

    auto issue = [&](int k0, float* base) {
        float* Ad = base;
        float* Bd = base + A_STG;
        #pragma unroll
        for (int it = 0; it < 4; it++) {
            const int ch = tid + it * 256;          // 1024 chunks
            const int row = ch >> 3, kq = ch & 7;
            cp_async16(Ad + row * AP + kq * 4,
                       A + (size_t)(m0 + row) * 256 + k0 + kq * 4);
        }
        if (TRANSB) {
            #pragma unroll
            for (int it = 0; it < 4; it++) {
                const int ch = tid + it * 256;
                const int row = ch >> 3, kq = ch & 7;
                cp_async16(Bd + row * BPT + kq * 4,
                           B + (size_t)(n0 + row) * 256 + k0 + kq * 4);
            }
        } else {
            #pragma unroll
            for (int it = 0; it < 4; it++) {
                const int ch = tid + it * 256;
                const int row = ch >> 5, nq = ch & 31;
                cp_async16(Bd + row * BPN + nq * 4,
                           B + (size_t)(k0 + row) * 256 + n0 + nq * 4);
            }
        }
    };

    const int r8  = lane & 7;
    const int sel = lane >> 3;
    uint32_t offA[2];
    #pragma unroll
    for (int mt = 0; mt < 2; mt++)
        offA[mt] = ((warp_m * 32 + mt * 16 + r8 + (sel & 1) * 8) * 9 + (sel >> 1)) * 16;
    uint32_t offB[4];
    #pragma unroll
    for (int pp = 0; pp < 4; pp++)
        offB[pp] = ((warp_n * 64 + (2 * pp + (sel >> 1)) * 8 + r8) * 9 + (sel & 1)) * 16;

    float acc[2][8][4];
    #pragma unroll
    for (int i = 0; i < 2; i++)
        #pragma unroll
        for (int j = 0; j < 8; j++)
            #pragma unroll
            for (int q = 0; q < 4; q++) acc[i][j][q] = 0.0f;

    issue(0,  smf);          cp_commit();
    issue(32, smf + STG);    cp_commit();

    #pragma unroll 1
    for (int iter = 0; iter < 8; iter++) {
        float* base = smf + (iter % 3) * STG;
        if (iter < 7) cp_wait<1>(); else cp_wait<0>();
        __syncthreads();   // orders staged data visibility AND previous-iter reads
        if (iter + 2 < 8) {
            issue((iter + 2) * 32, smf + ((iter + 2) % 3) * STG);
            cp_commit();
        }

        const uint32_t abase = (uint32_t)__cvta_generic_to_shared(base);
        const uint32_t bbase = (uint32_t)__cvta_generic_to_shared(base + A_STG);
        const float*   Bd    = base + A_STG;

        #pragma unroll
        for (int kb = 0; kb < 4; kb++) {
            const int kk = kb * 8;
            uint32_t a[2][4];
            #pragma unroll
            for (int mt = 0; mt < 2; mt++)
                ldsm_x4(a[mt][0], a[mt][1], a[mt][2], a[mt][3],
                        abase + offA[mt] + kb * 32);
            uint32_t bf[8][2];
            if (TRANSB) {
                #pragma unroll
                for (int pp = 0; pp < 4; pp++)
                    ldsm_x4(bf[2 * pp][0], bf[2 * pp][1],
                            bf[2 * pp + 1][0], bf[2 * pp + 1][1],
                            bbase + offB[pp] + kb * 32);
            } else {
                #pragma unroll
                for (int nt = 0; nt < 8; nt++) {
                    const int n = warp_n * 64 + nt * 8 + g;
                    bf[nt][0] = __float_as_uint(Bd[(kk + c) * BPN + n]);
                    bf[nt][1] = __float_as_uint(Bd[(kk + c + 4) * BPN + n]);
                }
            }
            #pragma unroll
            for (int mt = 0; mt < 2; mt++)
                #pragma unroll
                for (int nt = 0; nt < 8; nt++)
                    mma_tf32(acc[mt][nt], a[mt], bf[nt]);
        }
        // trailing __syncthreads removed: top-of-iter barrier already orders
        // buffer reuse (issue at iter i+1 targets buf i%3, read-complete by then)
    }

    #pragma unroll
    for (int mt = 0; mt < 2; mt++) {
        const int r0 = m0 + warp_m * 32 + mt * 16 + g;
        #pragma unroll
        for (int nt = 0; nt < 8; nt++) {
            const int col = n0 + warp_n * 64 + nt * 8 + 2 * c;
            float2 bv = make_float2(0.f, 0.f);
            if (p.bias) bv = *(const float2*)(p.bias + col);
            float2 v0 = make_float2(acc[mt][nt][0] + bv.x, acc[mt][nt][1] + bv.y);
            float2 v1 = make_float2(acc[mt][nt][2] + bv.x, acc[mt][nt][3] + bv.y);
            if (RELU) {
                v0.x = fmaxf(v0.x, 0.f); v0.y = fmaxf(v0.y, 0.f);
                v1.x = fmaxf(v1.x, 0.f); v1.y = fmaxf(v1.y, 0.f);
            }
            *(float2*)(p.C + (size_t)r0 * p.ldc + col)       = v0;
            *(float2*)(p.C + (size_t)(r0 + 8) * p.ldc + col) = v1;
            if (p.C2) {
                float2 w0 = make_float2(round_tf32(v0.x), round_tf32(v0.y));
                float2 w1v = make_float2(round_tf32(v1.x), round_tf32(v1.y));
                *(float2*)(p.C2 + (size_t)r0 * p.ldc + col)       = w0;
                *(float2*)(p.C2 + (size_t)(r0 + 8) * p.ldc + col) = w1v;
            }
        }
    }
}

// ======================= fused attention (scores+softmax+AV) ======================
// Mask applied SPARSELY: scatter-add compact edge values into S (smem).
#define SS_PITCH 516
#define KP 36
#define VP 40
#define Q_PITCH  36
#define FA_SMEM_FLOATS (64 * SS_PITCH + 512 * VP + 64 * Q_PITCH)
#define FA_SMEM_BYTES  (FA_SMEM_FLOATS * 4)

__global__ __launch_bounds__(512)
void fused_attn_kernel(const float* __restrict__ qkvA, const float* __restrict__ qkvB,
                       const int* __restrict__ srcp, const int* __restrict__ dstp,
                       const float* __restrict__ eval,   // [mod][b][e] or nullptr
                       float* __restrict__ OA, float* __restrict__ OB)
{
    const int z = blockIdx.z;
    const float* qkv  = z ? qkvB  : qkvA;
    float*       O    = z ? OB    : OA;

    extern __shared__ float sm[];
    float*    Ss  = sm;
    float*    KVs = sm + 64 * SS_PITCH;
    uint32_t* Ssu = (uint32_t*)Ss;
    uint32_t* KVu = (uint32_t*)KVs;
    uint32_t* Qu  = (uint32_t*)(KVs + 512 * VP);

    const int tid = threadIdx.x, wid = tid >> 5, lane = tid & 31;
    const int g = lane >> 2, c = lane & 3;
    const int bh = blockIdx.y, b = bh >> 3, h = bh & 7;
    const int i0 = blockIdx.x * 64;

    {
        const int m = tid >> 3, dq = (tid & 7) * 4;
        float4 v = *(const float4*)(qkv + (size_t)(b * NN_ + i0 + m) * 768 + h * DHH + dq);
        Qu[m * Q_PITCH + dq + 0] = f32_to_tf32(v.x);
        Qu[m * Q_PITCH + dq + 1] = f32_to_tf32(v.y);
        Qu[m * Q_PITCH + dq + 2] = f32_to_tf32(v.z);
        Qu[m * Q_PITCH + dq + 3] = f32_to_tf32(v.w);
    }
    #pragma unroll
    for (int it = 0; it < 8; it++) {
        const int f = tid + it * 512;
        const int j = f >> 3, dq = (f & 7) * 4;
        float4 v = *(const float4*)(qkv + (size_t)(b * NN_ + j) * 768 + 256 + h * DHH + dq);
        KVu[j * KP + dq + 0] = f32_to_tf32(v.x);
        KVu[j * KP + dq + 1] = f32_to_tf32(v.y);
        KVu[j * KP + dq + 2] = f32_to_tf32(v.z);
        KVu[j * KP + dq + 3] = f32_to_tf32(v.w);
    }
    __syncthreads();

    // ---- phase 1: S = Q K^T, warp w owns 32-col j-slab ----
    const int jb = wid * 32;
    float acc[4][4][4];
    #pragma unroll
    for (int mt = 0; mt < 4; mt++)
        #pragma unroll
        for (int nt = 0; nt < 4; nt++)
            #pragma unroll
            for (int q = 0; q < 4; q++) acc[mt][nt][q] = 0.0f;

    #pragma unroll
    for (int kb = 0; kb < 4; kb++) {
        const int kk = kb * 8;
        uint32_t a[4][4];
        #pragma unroll
        for (int mt = 0; mt < 4; mt++) {
            const int m = mt * 16 + g;
            a[mt][0] = Qu[m * Q_PITCH + kk + c];
            a[mt][1] = Qu[(m + 8) * Q_PITCH + kk + c];
            a[mt][2] = Qu[m * Q_PITCH + kk + c + 4];
            a[mt][3] = Qu[(m + 8) * Q_PITCH + kk + c + 4];
        }
        uint32_t bf[4][2];
        #pragma unroll
        for (int nt = 0; nt < 4; nt++) {
            const int j = jb + nt * 8 + g;
            bf[nt][0] = KVu[j * KP + kk + c];
            bf[nt][1] = KVu[j * KP + kk + c + 4];
        }
        #pragma unroll
        for (int mt = 0; mt < 4; mt++)
            #pragma unroll
            for (int nt = 0; nt < 4; nt++)
                mma_tf32(acc[mt][nt], a[mt], bf[nt]);
    }

    const float scale = 0.17677669529663687f;   // 1/sqrt(32)
    #pragma unroll
    for (int mt = 0; mt < 4; mt++) {
        const int r0 = mt * 16 + g;
        #pragma unroll
        for (int nt = 0; nt < 4; nt++) {
            const int col = jb + nt * 8 + 2 * c;
            Ss[r0 * SS_PITCH + col]           = acc[mt][nt][0] * scale;
            Ss[r0 * SS_PITCH + col + 1]       = acc[mt][nt][1] * scale;
            Ss[(r0 + 8) * SS_PITCH + col]     = acc[mt][nt][2] * scale;
            Ss[(r0 + 8) * SS_PITCH + col + 1] = acc[mt][nt][3] * scale;
        }
    }
    __syncthreads();   // S complete; K reads done

    // ---- sparse mask scatter-add (unique (s,d) per b -> race-free) ----
    if (eval) {
        const int tile = blockIdx.x;
        const int off = g_eoff[tile];
        const int cnt = g_eoff[tile + 1] - off;
        for (int t = tid; t < cnt; t += 512) {
            const int e = g_elist[off + t];
            const int s = srcp[e];
            const int d = dstp[e];
            const float v = eval[((size_t)z * BB + b) * EE + e];
            Ss[(s - i0) * SS_PITCH + d] += v;
        }
    }

    // ---- load V (512x32, tf32, pitch 40) ----
    #pragma unroll
    for (int it = 0; it < 8; it++) {
        const int f = tid + it * 512;
        const int j = f >> 3, dq = (f & 7) * 4;
        float4 v = *(const float4*)(qkv + (size_t)(b * NN_ + j) * 768 + 512 + h * DHH + dq);
        KVu[j * VP + dq + 0] = f32_to_tf32(v.x);
        KVu[j * VP + dq + 1] = f32_to_tf32(v.y);
        KVu[j * VP + dq + 2] = f32_to_tf32(v.z);
        KVu[j * VP + dq + 3] = f32_to_tf32(v.w);
    }
    __syncthreads();   // scatter + V complete

    // ---- softmax: warp handles rows [wid*4, wid*4+4) ----
    #pragma unroll
    for (int rr = 0; rr < 4; rr++) {
        const int row = wid * 4 + rr;
        float v[16];
        float mx = -1e30f;
        #pragma unroll
        for (int t = 0; t < 16; t++) {
            v[t] = Ss[row * SS_PITCH + lane + t * 32];
            mx = fmaxf(mx, v[t]);
        }
        #pragma unroll
        for (int o = 16; o > 0; o >>= 1) mx = fmaxf(mx, __shfl_xor_sync(0xffffffffu, mx, o));
        float s = 0.0f;
        #pragma unroll
        for (int t = 0; t < 16; t++) { v[t] = __expf(v[t] - mx); s += v[t]; }
        #pragma unroll
        for (int o = 16; o > 0; o >>= 1) s += __shfl_xor_sync(0xffffffffu, s, o);
        const float inv = 1.0f / s;
        #pragma unroll
        for (int t = 0; t < 16; t++)
            Ssu[row * SS_PITCH + lane + t * 32] = f32_to_tf32(v[t] * inv);
    }
    __syncthreads();   // P (tf32) + V ready

    // ---- phase 2: O = P V, 4 independent k-chains to break MMA latency ----
    const int mt2 = wid >> 2;
    const int nb  = (wid & 3) * 8;
    float o4[4][4] = {};
    const int m = mt2 * 16 + g;
    #pragma unroll 4
    for (int ks = 0; ks < 16; ks++) {
        #pragma unroll
        for (int q = 0; q < 4; q++) {
            const int kk = (q * 16 + ks) * 8;
            uint32_t a[4];
            a[0] = Ssu[m * SS_PITCH + kk + c];
            a[1] = Ssu[(m + 8) * SS_PITCH + kk + c];
            a[2] = Ssu[m * SS_PITCH + kk + c + 4];
            a[3] = Ssu[(m + 8) * SS_PITCH + kk + c + 4];
            uint32_t bb[2];
            bb[0] = KVu[(kk + c) * VP + nb + g];
            bb[1] = KVu[(kk + c + 4) * VP + nb + g];
            mma_tf32(o4[q], a, bb);
        }
    }
    float of[4];
    #pragma unroll
    for (int i = 0; i < 4; i++)
        of[i] = (o4[0][i] + o4[1][i]) + (o4[2][i] + o4[3][i]);

    const int r = b * NN_ + i0 + mt2 * 16 + g;
    const int colb = h * DHH + nb + 2 * c;
    *(float2*)(O + (size_t)r * DD + colb) =
        make_float2(round_tf32(of[0]), round_tf32(of[1]));
    *(float2*)(O + (size_t)(r + 8) * DD + colb) =
        make_float2(round_tf32(of[2]), round_tf32(of[3]));
}

// -------------------- edge MLP: sigmoid( relu(G1[src]+G2[dst]) . w2 + b2 ) --------
__global__ __launch_bounds__(256)
void edge_kernel(const float* __restrict__ G1a, const float* __restrict__ G2a,
                 const float* __restrict__ G1b, const float* __restrict__ G2b,
                 const int* __restrict__ src, const int* __restrict__ dst,
                 const float* __restrict__ w2, const float* __restrict__ b2,
                 float* __restrict__ Wa, float* __restrict__ Wb,
                 float* __restrict__ eval)
{
    const int z = blockIdx.z;
    const float* G1 = z ? G1b : G1a;
    const float* G2 = z ? G2b : G2a;
    float*       W  = z ? Wb  : Wa;
    const int b = blockIdx.y;
    const int wid = threadIdx.x >> 5, lane = threadIdx.x & 31;

    float4 wv0 = *(const float4*)(w2 + lane * 8);
    float4 wv1 = *(const float4*)(w2 + lane * 8 + 4);
    const float bias = b2[0];
    const int e0 = blockIdx.x * 64 + wid * 8;
    float* evz = eval + ((size_t)z * BB + b) * EE;

    #pragma unroll 1
    for (int i = 0; i < 8; i += 2) {
        const int eA = e0 + i, eB = e0 + i + 1;
        const int sA = src[eA], dA = dst[eA];
        const int sB = src[eB], dB = dst[eB];
        const float* g1A = G1 + ((size_t)b * NN_ + sA) * DD + lane * 8;
        const float* g2A = G2 + ((size_t)b * NN_ + dA) * DD + lane * 8;
        const float* g1B = G1 + ((size_t)b * NN_ + sB) * DD + lane * 8;
        const float* g2B = G2 + ((size_t)b * NN_ + dB) * DD + lane * 8;
        float4 a0A = *(const float4*)(g1A);
        float4 a1A = *(const float4*)(g1A + 4);
        float4 c0A = *(const float4*)(g2A);
        float4 c1A = *(const float4*)(g2A + 4);
        float4 a0B = *(const float4*)(g1B);
        float4 a1B = *(const float4*)(g1B + 4);
        float4 c0B = *(const float4*)(g2B);
        float4 c1B = *(const float4*)(g2B + 4);
        float accA = fmaxf(a0A.x + c0A.x, 0.f) * wv0.x + fmaxf(a0A.y + c0A.y, 0.f) * wv0.y
                   + fmaxf(a0A.z + c0A.z, 0.f) * wv0.z + fmaxf(a0A.w + c0A.w, 0.f) * wv0.w
                   + fmaxf(a1A.x + c1A.x, 0.f) * wv1.x + fmaxf(a1A.y + c1A.y, 0.f) * wv1.y
                   + fmaxf(a1A.z + c1A.z, 0.f) * wv1.z + fmaxf(a1A.w + c1A.w, 0.f) * wv1.w;
        float accB = fmaxf(a0B.x + c0B.x, 0.f) * wv0.x + fmaxf(a0B.y + c0B.y, 0.f) * wv0.y
                   + fmaxf(a0B.z + c0B.z, 0.f) * wv0.z + fmaxf(a0B.w + c0B.w, 0.f) * wv0.w
                   + fmaxf(a1B.x + c1B.x, 0.f) * wv1.x + fmaxf(a1B.y + c1B.y, 0.f) * wv1.y
                   + fmaxf(a1B.z + c1B.z, 0.f) * wv1.z + fmaxf(a1B.w + c1B.w, 0.f) * wv1.w;
        #pragma unroll
        for (int o = 16; o > 0; o >>= 1) {
            accA += __shfl_xor_sync(0xffffffffu, accA, o);
            accB += __shfl_xor_sync(0xffffffffu, accB, o);
        }
        if (lane == 0) {
            const float vA = 1.0f / (1.0f + __expf(-(accA + bias)));
            const float vB = 1.0f / (1.0f + __expf(-(accB + bias)));
            W[((size_t)b * NN_ + sA) * NN_ + dA] = vA;
            W[((size_t)b * NN_ + sB) * NN_ + dB] = vB;
            evz[eA] = vA;
            evz[eB] = vB;
        }
    }
}

// -------------------- consistency reduce: sigmoid(H . cw2 + cb2), batched ---------
__global__ __launch_bounds__(256)
void cons_reduce_kernel(const float* __restrict__ H0, const float* __restrict__ H1,
                        const float* __restrict__ cw2, const float* __restrict__ cb2,
                        float* __restrict__ o0, float* __restrict__ o1)
{
    const float* Hbuf = blockIdx.y ? H1 : H0;
    float* out        = blockIdx.y ? o1 : o0;
    __shared__ float red[256];
    const int row = blockIdx.x;
    const int t = threadIdx.x;
    red[t] = Hbuf[(size_t)row * DD + t] * __ldg(cw2 + t);
    __syncthreads();
    for (int s = 128; s > 0; s >>= 1) { if (t < s) red[t] += red[t + s]; __syncthreads(); }
    if (t == 0) out[row] = 1.0f / (1.0f + __expf(-(red[0] + cb2[0])));
}

// ===================================================================================
extern "C" void kernel_launch(void* const* d_in, const int* in_sizes, int n_in,
                              void* d_out, int out_size)
{
    const float* img   = (const float*)d_in[0];
    const float* txt   = (const float*)d_in[1];
    const int*   src   = (const int*)d_in[2];
    const int*   dst   = (const int*)d_in[3];
    const float* w1    = (const float*)d_in[4];
    const float* b1    = (const float*)d_in[5];
    const float* w2    = (const float*)d_in[6];
    const float* b2    = (const float*)d_in[7];
    const float* in_w  = (const float*)d_in[8];
    const float* in_b  = (const float*)d_in[9];
    const float* out_w = (const float*)d_in[10];
    const float* out_b = (const float*)d_in[11];
    const float* cw1   = (const float*)d_in[12];
    const float* cb1   = (const float*)d_in[13];
    const float* cw2   = (const float*)d_in[14];
    const float* cb2   = (const float*)d_in[15];
    float* out = (float*)d_out;

    float *qkv0, *qkv1, *attn0, *attn1, *G1i, *G2i, *G1t, *G2t, *H0, *H1;
    float *imgR, *txtR, *w1R, *inwR, *outwR, *cw1R, *aimgR, *atxtR, *evalp;
    cudaGetSymbolAddress((void**)&qkv0,  g_qkv0);
    cudaGetSymbolAddress((void**)&qkv1,  g_qkv1);
    cudaGetSymbolAddress((void**)&attn0, g_attn0);
    cudaGetSymbolAddress((void**)&attn1, g_attn1);
    cudaGetSymbolAddress((void**)&G1i,   g_G1i);
    cudaGetSymbolAddress((void**)&G2i,   g_G2i);
    cudaGetSymbolAddress((void**)&G1t,   g_G1t);
    cudaGetSymbolAddress((void**)&G2t,   g_G2t);
    cudaGetSymbolAddress((void**)&H0,    g_H0);
    cudaGetSymbolAddress((void**)&H1,    g_H1);
    cudaGetSymbolAddress((void**)&imgR,  g_imgR);
    cudaGetSymbolAddress((void**)&txtR,  g_txtR);
    cudaGetSymbolAddress((void**)&w1R,   g_w1R);
    cudaGetSymbolAddress((void**)&inwR,  g_inwR);
    cudaGetSymbolAddress((void**)&outwR, g_outwR);
    cudaGetSymbolAddress((void**)&cw1R,  g_cw1R);
    cudaGetSymbolAddress((void**)&aimgR, g_aimgR);
    cudaGetSymbolAddress((void**)&atxtR, g_atxtR);
    cudaGetSymbolAddress((void**)&evalp, g_eval);

    cudaFuncSetAttribute(fused_attn_kernel,
                         cudaFuncAttributeMaxDynamicSharedMemorySize, FA_SMEM_BYTES);
    cudaFuncSetAttribute(gemm_tf32_kernel<true, false>,
                         cudaFuncAttributeMaxDynamicSharedMemorySize, SMEM_GEMM_T);
    cudaFuncSetAttribute(gemm_tf32_kernel<false, false>,
                         cudaFuncAttributeMaxDynamicSharedMemorySize, SMEM_GEMM_N);
    cudaFuncSetAttribute(gemm_tf32_kernel<false, true>,
                         cudaFuncAttributeMaxDynamicSharedMemorySize, SMEM_GEMM_N);

    // ---- fork/join infra (created once; reused -> identical captured graphs) ----
    static cudaStream_t s_aux = nullptr;
    static cudaEvent_t ev_f1 = nullptr, ev_j1 = nullptr, ev_f2 = nullptr, ev_j2 = nullptr;
    if (!s_aux) {
        cudaStreamCreateWithFlags(&s_aux, cudaStreamNonBlocking);
        cudaEventCreateWithFlags(&ev_f1, cudaEventDisableTiming);
        cudaEventCreateWithFlags(&ev_j1, cudaEventDisableTiming);
        cudaEventCreateWithFlags(&ev_f2, cudaEventDisableTiming);
        cudaEventCreateWithFlags(&ev_j2, cudaEventDisableTiming);
    }

    const dim3 blk(256);
    const dim3 blkfa(512);

    // ---- zero the two adjacency-weight output blocks ----
    cudaMemsetAsync(out + O_IW, 0, (size_t)2 * BB * NN_ * NN_ * sizeof(float), 0);

    // ---- pre-round all static GEMM inputs to tf32 ----
    {
        RoundBatch rb;
        rb.s[0] = img;   rb.d[0] = imgR;  rb.n[0] = BN * DD;
        rb.s[1] = txt;   rb.d[1] = txtR;  rb.n[1] = BN * DD;
        rb.s[2] = w1;    rb.d[2] = w1R;   rb.n[2] = 512 * 256;
        rb.s[3] = in_w;  rb.d[3] = inwR;  rb.n[3] = 768 * 256;
        rb.s[4] = out_w; rb.d[4] = outwR; rb.n[4] = 256 * 256;
        rb.s[5] = cw1;   rb.d[5] = cw1R;  rb.n[5] = 256 * 256;
        round_kernel<<<dim3(512, 6), blk>>>(rb);
    }
    bucket_kernel<<<1, 256>>>(src);

    // ===== fork 1: qkv projections run concurrent with causal-proj + edge =====
    cudaEventRecord(ev_f1, 0);
    cudaStreamWaitEvent(s_aux, ev_f1, 0);
    {
        GemmBatch gb;
        gb.p[0] = { imgR, inwR, in_b, qkv0, nullptr, 768, 768 };
        gb.p[1] = { txtR, inwR, in_b, qkv1, nullptr, 768, 768 };
        gb.p[2] = gb.p[0]; gb.p[3] = gb.p[0];
        gemm_tf32_kernel<true, false><<<dim3(6, 64, 2), blk, SMEM_GEMM_T, s_aux>>>(gb);
    }
    cudaEventRecord(ev_j1, s_aux);

    // ---- main stream: causal-weight projections + edge MLP ----
    {
        GemmBatch gb;
        gb.p[0] = { imgR, w1R,             b1,      G1i, nullptr, 256, 256 };
        gb.p[1] = { imgR, w1R + 256 * 256, nullptr, G2i, nullptr, 256, 256 };
        gb.p[2] = { txtR, w1R,             b1,      G1t, nullptr, 256, 256 };
        gb.p[3] = { txtR, w1R + 256 * 256, nullptr, G2t, nullptr, 256, 256 };
        gemm_tf32_kernel<false, false><<<dim3(2, 64, 4), blk, SMEM_GEMM_N>>>(gb);
    }
    edge_kernel<<<dim3(EE / 64, BB, 2), blk>>>(G1i, G2i, G1t, G2t, src, dst, w2, b2,
                                               out + O_IW, out + O_TW, evalp);
    cudaStreamWaitEvent(0, ev_j1, 0);    // join: fa needs qkv + eval

    // ---- fused attention MHA1+MHA2 (sparse mask) ----
    fused_attn_kernel<<<dim3(8, 128, 2), blkfa, FA_SMEM_BYTES>>>(
        qkv0, qkv1, src, dst, evalp, attn0, attn1);
    // ---- out-proj MHA1+MHA2 (also emits tf32-rounded copies) ----
    {
        GemmBatch gb;
        gb.p[0] = { attn0, outwR, out_b, out + O_AIMG, aimgR, 256, 256 };
        gb.p[1] = { attn1, outwR, out_b, out + O_ATXT, atxtR, 256, 256 };
        gb.p[2] = gb.p[0]; gb.p[3] = gb.p[0];
        gemm_tf32_kernel<true, false><<<dim3(2, 64, 2), blk, SMEM_GEMM_T>>>(gb);
    }

    // ===== fork 2: consistency chain concurrent with MHA3 chain =====
    cudaEventRecord(ev_f2, 0);
    cudaStreamWaitEvent(s_aux, ev_f2, 0);
    {
        GemmBatch gb;
        gb.p[0] = { aimgR, cw1R, cb1, H0, nullptr, 256, 256 };
        gb.p[1] = { atxtR, cw1R, cb1, H1, nullptr, 256, 256 };
        gb.p[2] = gb.p[0]; gb.p[3] = gb.p[0];
        gemm_tf32_kernel<false, true><<<dim3(2, 64, 2), blk, SMEM_GEMM_N, s_aux>>>(gb);
    }
    cons_reduce_kernel<<<dim3(BN, 2), blk, 0, s_aux>>>(H0, H1, cw2, cb2,
                                                       out + O_IC, out + O_TC);
    cudaEventRecord(ev_j2, s_aux);

    // ---- main stream: MHA3 ----
    {
        GemmBatch gb;
        gb.p[0] = { aimgR, inwR,             in_b,       qkv0,       nullptr, 256, 768 };
        gb.p[1] = { atxtR, inwR + 256 * 256, in_b + 256, qkv0 + 256, nullptr, 512, 768 };
        gb.p[2] = gb.p[0]; gb.p[3] = gb.p[0];
        gemm_tf32_kernel<true, false><<<dim3(4, 64, 2), blk, SMEM_GEMM_T>>>(gb);
    }
    fused_attn_kernel<<<dim3(8, 128, 1), blkfa, FA_SMEM_BYTES>>>(
        qkv0, qkv0, src, dst, nullptr, attn0, attn0);
    {
        GemmBatch gb;
        gb.p[0] = { attn0, outwR, out_b, out + O_XMOD, nullptr, 256, 256 };
        gb.p[1] = gb.p[0]; gb.p[2] = gb.p[0]; gb.p[3] = gb.p[0];
        gemm_tf32_kernel<true, false><<<dim3(2, 64, 1), blk, SMEM_GEMM_T>>>(gb);
    }
    cudaStreamWaitEvent(0, ev_j2, 0);    // join consistency chain before capture ends
}